// round 2
// baseline (speedup 1.0000x reference)
#include <cuda_runtime.h>
#include <math.h>

// ---------------------------------------------------------------------------
// DirectRegressionHead: 2-layer GRU encoder (7 steps) + 12-step GRU decoder
// with feedback projections. B=32768, H=256, CTX=128, PRED=12. All fp32.
// ---------------------------------------------------------------------------

#define BMAX 32768
#define HDIM 256
#define CTXD 128
#define PRED 12

// --- static device scratch (no allocation allowed) ---
__device__ float g_h0a[BMAX * HDIM];
__device__ float g_h0b[BMAX * HDIM];
__device__ float g_h1a[BMAX * HDIM];
__device__ float g_h1b[BMAX * HDIM];
__device__ float g_obsin[16 * BMAX * 6];   // [t][b][6]
__device__ float g_ctxp[BMAX * CTXD];      // ctx @ Cw.T + cb
__device__ float g_dynA[BMAX * 6];
__device__ float g_dynB[BMAX * 6];

// ---------------------------------------------------------------------------
// zero kernel (grid-stride, float4)
// ---------------------------------------------------------------------------
__global__ void zero_kernel(float* __restrict__ p, int n) {
    int stride = gridDim.x * blockDim.x;
    for (int i = blockIdx.x * blockDim.x + threadIdx.x; i * 4 < n; i += stride) {
        ((float4*)p)[i] = make_float4(0.f, 0.f, 0.f, 0.f);
    }
}

// ---------------------------------------------------------------------------
// prep: vel / me_vel / acc sequences + initial dynamic-6 vector
// obs_traj, obs_Me: [T][B][2] time-major
// obsin[t][b][6] = (vel, me_vel, acc_padded); dyn[b][6] = (lv, la, lm)
// ---------------------------------------------------------------------------
__global__ void prep_kernel(const float* __restrict__ traj,
                            const float* __restrict__ me,
                            float* __restrict__ obsin,
                            float* __restrict__ dyn, int B, int T) {
    int b = blockIdx.x * blockDim.x + threadIdx.x;
    if (b >= B) return;
    float vx[16], vy[16], mx[16], my_[16];
    int TS = T - 1;           // 7
    if (TS > 16) TS = 16;
    for (int t = 0; t < TS; t++) {
        vx[t]  = traj[((size_t)(t + 1) * B + b) * 2 + 0] - traj[((size_t)t * B + b) * 2 + 0];
        vy[t]  = traj[((size_t)(t + 1) * B + b) * 2 + 1] - traj[((size_t)t * B + b) * 2 + 1];
        mx[t]  = me[((size_t)(t + 1) * B + b) * 2 + 0] - me[((size_t)t * B + b) * 2 + 0];
        my_[t] = me[((size_t)(t + 1) * B + b) * 2 + 1] - me[((size_t)t * B + b) * 2 + 1];
    }
    for (int t = 0; t < TS; t++) {
        int ta = (t == 0) ? 1 : t;            // acc pad: acc[0] duplicated
        float ax = vx[ta] - vx[ta - 1];
        float ay = vy[ta] - vy[ta - 1];
        float* o = obsin + ((size_t)t * B + b) * 6;
        o[0] = vx[t]; o[1] = vy[t];
        o[2] = mx[t]; o[3] = my_[t];
        o[4] = ax;    o[5] = ay;
    }
    // decoder init: cv = last_vel, ca = last_acc, cm = last_me
    dyn[(size_t)b * 6 + 0] = vx[TS - 1];
    dyn[(size_t)b * 6 + 1] = vy[TS - 1];
    dyn[(size_t)b * 6 + 2] = vx[TS - 1] - vx[TS - 2];
    dyn[(size_t)b * 6 + 3] = vy[TS - 1] - vy[TS - 2];
    dyn[(size_t)b * 6 + 4] = mx[TS - 1];
    dyn[(size_t)b * 6 + 5] = my_[TS - 1];
}

// ---------------------------------------------------------------------------
// ctx projection: ctxp[B,128] = ctx[B,128] @ Cw.T + cb
// block: 256 thr, tile 64 rows x 128 cols, K=128
// ---------------------------------------------------------------------------
__global__ __launch_bounds__(256) void ctx_kernel(const float* __restrict__ ctx,
                                                  const float* __restrict__ Cw,
                                                  const float* __restrict__ cb,
                                                  float* __restrict__ outp, int B) {
    __shared__ float Cs[64][128];
    __shared__ float Wc[16][128];
    int tid = threadIdx.x;
    int m0 = blockIdx.x * 64;
    for (int i = tid; i < 64 * 128 / 4; i += 256) {
        int m = m0 + (i * 4) / 128;
        float4 v = make_float4(0.f, 0.f, 0.f, 0.f);
        if (m < B) v = *(const float4*)&ctx[(size_t)m0 * 128 + i * 4];
        ((float4*)Cs)[i] = v;
    }
    __syncthreads();
    int w = tid >> 5, lane = tid & 31;
    float acc[8][4];
#pragma unroll
    for (int i = 0; i < 8; i++)
#pragma unroll
        for (int u = 0; u < 4; u++) acc[i][u] = 0.f;

    for (int k0 = 0; k0 < 128; k0 += 16) {
        for (int i = tid; i < 16 * 128; i += 256) {
            int kk = i & 15, u = i >> 4;
            Wc[kk][u] = Cw[(size_t)u * 128 + k0 + kk];
        }
        __syncthreads();
#pragma unroll
        for (int kk = 0; kk < 16; kk++) {
            float wv[4];
#pragma unroll
            for (int u = 0; u < 4; u++) wv[u] = Wc[kk][lane * 4 + u];
#pragma unroll
            for (int i = 0; i < 8; i++) {
                float a = Cs[w * 8 + i][k0 + kk];
#pragma unroll
                for (int u = 0; u < 4; u++) acc[i][u] += a * wv[u];
            }
        }
        __syncthreads();
    }
#pragma unroll
    for (int i = 0; i < 8; i++) {
        int m = m0 + w * 8 + i;
        if (m >= B) continue;
#pragma unroll
        for (int u = 0; u < 4; u++) {
            int ug = lane * 4 + u;
            outp[(size_t)m * 128 + ug] = acc[i][u] + cb[ug];
        }
    }
}

// ---------------------------------------------------------------------------
// Generic fused GRU cell.
// h' = (1-z)*n + z*h ;  r=sig(gi_r+gh_r) z=sig(gi_z+gh_z)
// n = tanh(gi_n + r*gh_n), gi = [X1|X2] @ Wih.T + bih, gh = h @ Whh.T + bhh
// Block tile: 128 rows x 32 gate-cols, 4 accumulator planes (r,z,ig,hg).
// ---------------------------------------------------------------------------
#define KC 16
#define MT 128
#define NT 32

#define SEG(XPTR, LDX, WPTR, LDW, COFF, KDIM, P2ACC)                                   \
    for (int k0 = 0; k0 < (KDIM); k0 += KC) {                                          \
        for (int i = tid; i < KC * MT; i += 256) {                                     \
            int kk = i & (KC - 1); int mm = i >> 4;                                    \
            int m = m0 + mm; int k = k0 + kk;                                          \
            As[kk][mm] = (m < B && k < (KDIM)) ? (XPTR)[(size_t)m * (LDX) + k] : 0.f;  \
        }                                                                              \
        for (int i = tid; i < 3 * KC * NT; i += 256) {                                 \
            int kk = i & (KC - 1); int r_ = i >> 4;                                    \
            int jj = r_ & (NT - 1); int p = r_ >> 5;                                   \
            int k = k0 + kk;                                                           \
            Ws[p][kk][jj] = (k < (KDIM))                                               \
                ? (WPTR)[(size_t)(p * 256 + n0 + jj) * (LDW) + (COFF) + k] : 0.f;      \
        }                                                                              \
        __syncthreads();                                                               \
        _Pragma("unroll")                                                              \
        for (int kk = 0; kk < KC; kk++) {                                              \
            float4 a0 = *(const float4*)&As[kk][ty * 8];                               \
            float4 a1 = *(const float4*)&As[kk][ty * 8 + 4];                           \
            float2 w0 = *(const float2*)&Ws[0][kk][tx * 2];                            \
            float2 w1 = *(const float2*)&Ws[1][kk][tx * 2];                            \
            float2 w2 = *(const float2*)&Ws[2][kk][tx * 2];                            \
            float a[8] = {a0.x, a0.y, a0.z, a0.w, a1.x, a1.y, a1.z, a1.w};             \
            _Pragma("unroll")                                                          \
            for (int i = 0; i < 8; i++) {                                              \
                aR[i][0] += a[i] * w0.x;  aR[i][1] += a[i] * w0.y;                     \
                aZ[i][0] += a[i] * w1.x;  aZ[i][1] += a[i] * w1.y;                     \
                P2ACC[i][0] += a[i] * w2.x;  P2ACC[i][1] += a[i] * w2.y;               \
            }                                                                          \
        }                                                                              \
        __syncthreads();                                                               \
    }

__global__ __launch_bounds__(256) void gru_cell_kernel(
    const float* __restrict__ X1, int d1,
    const float* __restrict__ X2, int d2,
    const float* __restrict__ Hin,
    const float* __restrict__ Wih, int ldw_ih,
    const float* __restrict__ Whh,
    const float* __restrict__ bih, const float* __restrict__ bhh,
    float* __restrict__ Hout, int B) {
    __shared__ float As[KC][MT];
    __shared__ float Ws[3][KC][NT];
    int tid = threadIdx.x;
    int tx = tid & 15;       // 16 col-groups of 2
    int ty = tid >> 4;       // 16 row-groups of 8
    int m0 = blockIdx.x * MT;
    int n0 = blockIdx.y * NT;

    float aR[8][2], aZ[8][2], aIG[8][2], aHG[8][2];
#pragma unroll
    for (int i = 0; i < 8; i++)
#pragma unroll
        for (int j = 0; j < 2; j++) { aR[i][j] = 0.f; aZ[i][j] = 0.f; aIG[i][j] = 0.f; aHG[i][j] = 0.f; }

    // input segment(s): planes r,z,ig
    SEG(X1, d1, Wih, ldw_ih, 0, d1, aIG)
    if (X2 != nullptr && d2 > 0) {
        SEG(X2, d2, Wih, ldw_ih, d1, d2, aIG)
    }
    // hidden segment: planes r,z,hg
    SEG(Hin, 256, Whh, 256, 0, 256, aHG)

#pragma unroll
    for (int i = 0; i < 8; i++) {
        int m = m0 + ty * 8 + i;
        if (m >= B) continue;
#pragma unroll
        for (int j = 0; j < 2; j++) {
            int jg = n0 + tx * 2 + j;
            float r = 1.f / (1.f + expf(-(aR[i][j] + bih[jg] + bhh[jg])));
            float z = 1.f / (1.f + expf(-(aZ[i][j] + bih[256 + jg] + bhh[256 + jg])));
            float n = tanhf(aIG[i][j] + bih[512 + jg] + r * (aHG[i][j] + bhh[512 + jg]));
            float hp = Hin[(size_t)m * 256 + jg];
            Hout[(size_t)m * 256 + jg] = (1.f - z) * n + z * hp;
        }
    }
}

// ---------------------------------------------------------------------------
// projection: delta = GELU(h@P1.T+p1b)@P2.T+p2b ; acorr = GELU(h@A1.T+a1b)@A2.T+a2b
// writes out[b, t, 0:4] = delta; dyn_out[b] = (delta01, acorr01, delta23)
// Block: 64 samples, 256 thr, stage1 = GEMM [64 x 192] K=256 (exact erf GELU)
// ---------------------------------------------------------------------------
#define PROJ_SMEM ((64 * 256 + 64 * 196 + 16 * 192) * 4)

__global__ __launch_bounds__(256) void proj_kernel(
    const float* __restrict__ H, const float* __restrict__ P1, const float* __restrict__ p1b,
    const float* __restrict__ P2, const float* __restrict__ p2b,
    const float* __restrict__ A1, const float* __restrict__ a1b,
    const float* __restrict__ A2, const float* __restrict__ a2b,
    float* __restrict__ out, float* __restrict__ dyn, int B, int tstep) {
    extern __shared__ float ps[];
    float* Hs = ps;                    // [64][256]
    float* D1 = ps + 64 * 256;         // [64][196] (padded stride)
    float* Wsh = D1 + 64 * 196;        // [16][192]
    int tid = threadIdx.x;
    int m0 = blockIdx.x * 64;

    for (int i = tid; i < 64 * 256 / 4; i += 256) {
        int m = m0 + (i * 4) / 256;
        float4 v = make_float4(0.f, 0.f, 0.f, 0.f);
        if (m < B) v = *(const float4*)&H[(size_t)m0 * 256 + i * 4];
        ((float4*)Hs)[i] = v;
    }
    __syncthreads();

    int w = tid >> 5, lane = tid & 31;
    float acc[8][6];
#pragma unroll
    for (int i = 0; i < 8; i++)
#pragma unroll
        for (int u = 0; u < 6; u++) acc[i][u] = 0.f;

    for (int k0 = 0; k0 < 256; k0 += 16) {
        for (int i = tid; i < 16 * 192; i += 256) {
            int kk = i & 15, u = i >> 4;
            Wsh[kk * 192 + u] = (u < 128) ? P1[(size_t)u * 256 + k0 + kk]
                                          : A1[(size_t)(u - 128) * 256 + k0 + kk];
        }
        __syncthreads();
#pragma unroll
        for (int kk = 0; kk < 16; kk++) {
            float wv[6];
#pragma unroll
            for (int u = 0; u < 6; u++) wv[u] = Wsh[kk * 192 + lane * 6 + u];
#pragma unroll
            for (int i = 0; i < 8; i++) {
                float a = Hs[(w * 8 + i) * 256 + k0 + kk];
#pragma unroll
                for (int u = 0; u < 6; u++) acc[i][u] += a * wv[u];
            }
        }
        __syncthreads();
    }
#pragma unroll
    for (int i = 0; i < 8; i++) {
        int s = w * 8 + i;
#pragma unroll
        for (int u = 0; u < 6; u++) {
            int uu = lane * 6 + u;
            float b = (uu < 128) ? p1b[uu] : a1b[uu - 128];
            float v = acc[i][u] + b;
            D1[s * 196 + uu] = v * normcdff(v);   // exact GELU: x * Phi(x)
        }
    }
    __syncthreads();

    {   // delta head: 64 samples x 4 outputs, dot over 128
        int s = tid >> 2, o = tid & 3;
        float a = p2b[o];
        for (int k = 0; k < 128; k++) a += D1[s * 196 + k] * P2[(size_t)o * 128 + k];
        int m = m0 + s;
        if (m < B) {
            out[(size_t)m * 48 + tstep * 4 + o] = a;
            dyn[(size_t)m * 6 + (o < 2 ? o : o + 2)] = a;   // cv -> 0,1 ; cm -> 4,5
        }
    }
    if (tid < 128) {   // accel head: 64 samples x 2 outputs, dot over 64
        int s = tid >> 1, o = tid & 1;
        float a = a2b[o];
        for (int k = 0; k < 64; k++) a += D1[s * 196 + 128 + k] * A2[(size_t)o * 64 + k];
        int m = m0 + s;
        if (m < B) dyn[(size_t)m * 6 + 2 + o] = a;          // ca -> 2,3
    }
}

// ---------------------------------------------------------------------------
// launch
// ---------------------------------------------------------------------------
extern "C" void kernel_launch(void* const* d_in, const int* in_sizes, int n_in,
                              void* d_out, int out_size) {
    const float* ctx      = (const float*)d_in[0];
    const float* obs_traj = (const float*)d_in[1];
    const float* obs_Me   = (const float*)d_in[2];
    const float* Wih0 = (const float*)d_in[3];
    const float* Whh0 = (const float*)d_in[4];
    const float* bih0 = (const float*)d_in[5];
    const float* bhh0 = (const float*)d_in[6];
    const float* Wih1 = (const float*)d_in[7];
    const float* Whh1 = (const float*)d_in[8];
    const float* bih1 = (const float*)d_in[9];
    const float* bhh1 = (const float*)d_in[10];
    const float* Wihs = (const float*)d_in[11];
    const float* Whhs = (const float*)d_in[12];
    const float* bihs = (const float*)d_in[13];
    const float* bhhs = (const float*)d_in[14];
    const float* P1  = (const float*)d_in[15];
    const float* p1b = (const float*)d_in[16];
    const float* P2  = (const float*)d_in[17];
    const float* p2b = (const float*)d_in[18];
    const float* A1  = (const float*)d_in[19];
    const float* a1b = (const float*)d_in[20];
    const float* A2  = (const float*)d_in[21];
    const float* a2b = (const float*)d_in[22];
    const float* Cw  = (const float*)d_in[23];
    const float* cb  = (const float*)d_in[24];
    float* out = (float*)d_out;

    int B = in_sizes[0] / CTXD;
    if (B > BMAX) B = BMAX;
    int T = in_sizes[1] / (2 * B);
    int TS = T - 1;

    float *h0a, *h0b, *h1a, *h1b, *obsin, *ctxp, *dynA, *dynB;
    cudaGetSymbolAddress((void**)&h0a, g_h0a);
    cudaGetSymbolAddress((void**)&h0b, g_h0b);
    cudaGetSymbolAddress((void**)&h1a, g_h1a);
    cudaGetSymbolAddress((void**)&h1b, g_h1b);
    cudaGetSymbolAddress((void**)&obsin, g_obsin);
    cudaGetSymbolAddress((void**)&ctxp, g_ctxp);
    cudaGetSymbolAddress((void**)&dynA, g_dynA);
    cudaGetSymbolAddress((void**)&dynB, g_dynB);

    cudaFuncSetAttribute(proj_kernel, cudaFuncAttributeMaxDynamicSharedMemorySize, PROJ_SMEM);

    dim3 cgrid((B + MT - 1) / MT, HDIM / NT);   // (256, 8) for B=32768

    zero_kernel<<<264, 256>>>(h0a, B * HDIM);
    zero_kernel<<<264, 256>>>(h1a, B * HDIM);
    prep_kernel<<<(B + 255) / 256, 256>>>(obs_traj, obs_Me, obsin, dynA, B, T);
    ctx_kernel<<<(B + 63) / 64, 256>>>(ctx, Cw, cb, ctxp, B);

    // encoder: interleave layer0 / layer1 per timestep
    float *h0i = h0a, *h0o = h0b, *h1i = h1a, *h1o = h1b;
    for (int t = 0; t < TS; t++) {
        gru_cell_kernel<<<cgrid, 256>>>(obsin + (size_t)t * B * 6, 6, nullptr, 0,
                                        h0i, Wih0, 6, Whh0, bih0, bhh0, h0o, B);
        gru_cell_kernel<<<cgrid, 256>>>(h0o, 256, nullptr, 0,
                                        h1i, Wih1, 256, Whh1, bih1, bhh1, h1o, B);
        float* t0 = h0i; h0i = h0o; h0o = t0;
        float* t1 = h1i; h1i = h1o; h1o = t1;
    }

    // decoder: h starts at final layer-1 state (h1i after swaps)
    float* dhi = h1i;
    float* dho = h1o;
    float* dyi = dynA;
    float* dyo = dynB;
    for (int s = 0; s < PRED; s++) {
        gru_cell_kernel<<<cgrid, 256>>>(ctxp, 128, dyi, 6,
                                        dhi, Wihs, 134, Whhs, bihs, bhhs, dho, B);
        proj_kernel<<<(B + 63) / 64, 256, PROJ_SMEM>>>(dho, P1, p1b, P2, p2b,
                                                       A1, a1b, A2, a2b,
                                                       out, dyo, B, s);
        float* td = dhi; dhi = dho; dho = td;
        float* ty_ = dyi; dyi = dyo; dyo = ty_;
    }
}

// round 3
// speedup vs baseline: 2.6786x; 2.6786x over previous
#include <cuda_runtime.h>
#include <cuda_bf16.h>
#include <math.h>
#include <stdint.h>

// ---------------------------------------------------------------------------
// DirectRegressionHead: 2-layer GRU encoder (7 steps) + 12-step GRU decoder.
// B=32768, H=256, CTX=128, PRED=12.
// GRU cell GEMMs: bf16x3 split-precision tensor-core (mma.sync.m16n8k16),
// fp32 accumulate, fused gate epilogue. Projections stay fp32.
// ---------------------------------------------------------------------------

#define BMAX 32768
#define HDIM 256
#define CTXD 128
#define PRED 12
#define STR 72            // smem tile k-stride in bf16 (64 + 8 pad)

// packed weight layout (elements, bf16): hi plane then lo plane at +WTOT
#define O_WIH0 0L          // 768 x 64   (K=6 padded)
#define O_WHH0 49152L      // 768 x 256
#define O_WIH1 245760L     // 768 x 256
#define O_WHH1 442368L     // 768 x 256
#define O_WIHS 638976L     // 768 x 192  (K=134 padded)
#define O_WHHS 786432L     // 768 x 256
#define WTOT   983040L

// --- static device scratch ---
__device__ float g_h0a[BMAX * HDIM];
__device__ float g_h0b[BMAX * HDIM];
__device__ float g_h1a[BMAX * HDIM];
__device__ float g_h1b[BMAX * HDIM];
__device__ float g_obsin[16 * BMAX * 6];
__device__ float g_ctxp[BMAX * CTXD];
__device__ float g_dynA[BMAX * 6];
__device__ float g_dynB[BMAX * 6];
__device__ __nv_bfloat16 g_wpack[2 * WTOT];

// ---------------------------------------------------------------------------
__global__ void zero_kernel(float* __restrict__ p, int n) {
    int stride = gridDim.x * blockDim.x;
    for (int i = blockIdx.x * blockDim.x + threadIdx.x; i * 4 < n; i += stride)
        ((float4*)p)[i] = make_float4(0.f, 0.f, 0.f, 0.f);
}

// pack one weight matrix [768, K] -> hi/lo bf16 at wp[dst], row stride Kpad
__global__ void pack_kernel(const float* __restrict__ W, int K, int Kpad,
                            long dst, __nv_bfloat16* __restrict__ wp) {
    int i = blockIdx.x * blockDim.x + threadIdx.x;
    if (i >= 768 * Kpad) return;
    int r = i / Kpad, k = i - r * Kpad;
    float v = (k < K) ? W[(size_t)r * K + k] : 0.f;
    __nv_bfloat16 h = __float2bfloat16(v);
    wp[dst + i] = h;
    wp[WTOT + dst + i] = __float2bfloat16(v - __bfloat162float(h));
}

// ---------------------------------------------------------------------------
__global__ void prep_kernel(const float* __restrict__ traj,
                            const float* __restrict__ me,
                            float* __restrict__ obsin,
                            float* __restrict__ dyn, int B, int T) {
    int b = blockIdx.x * blockDim.x + threadIdx.x;
    if (b >= B) return;
    float vx[16], vy[16], mx[16], my_[16];
    int TS = T - 1;
    if (TS > 16) TS = 16;
    for (int t = 0; t < TS; t++) {
        vx[t]  = traj[((size_t)(t + 1) * B + b) * 2 + 0] - traj[((size_t)t * B + b) * 2 + 0];
        vy[t]  = traj[((size_t)(t + 1) * B + b) * 2 + 1] - traj[((size_t)t * B + b) * 2 + 1];
        mx[t]  = me[((size_t)(t + 1) * B + b) * 2 + 0] - me[((size_t)t * B + b) * 2 + 0];
        my_[t] = me[((size_t)(t + 1) * B + b) * 2 + 1] - me[((size_t)t * B + b) * 2 + 1];
    }
    for (int t = 0; t < TS; t++) {
        int ta = (t == 0) ? 1 : t;
        float ax = vx[ta] - vx[ta - 1];
        float ay = vy[ta] - vy[ta - 1];
        float* o = obsin + ((size_t)t * B + b) * 6;
        o[0] = vx[t]; o[1] = vy[t];
        o[2] = mx[t]; o[3] = my_[t];
        o[4] = ax;    o[5] = ay;
    }
    dyn[(size_t)b * 6 + 0] = vx[TS - 1];
    dyn[(size_t)b * 6 + 1] = vy[TS - 1];
    dyn[(size_t)b * 6 + 2] = vx[TS - 1] - vx[TS - 2];
    dyn[(size_t)b * 6 + 3] = vy[TS - 1] - vy[TS - 2];
    dyn[(size_t)b * 6 + 4] = mx[TS - 1];
    dyn[(size_t)b * 6 + 5] = my_[TS - 1];
}

// ---------------------------------------------------------------------------
__global__ __launch_bounds__(256) void ctx_kernel(const float* __restrict__ ctx,
                                                  const float* __restrict__ Cw,
                                                  const float* __restrict__ cb,
                                                  float* __restrict__ outp, int B) {
    __shared__ float Cs[64][128];
    __shared__ float Wc[16][128];
    int tid = threadIdx.x;
    int m0 = blockIdx.x * 64;
    for (int i = tid; i < 64 * 128 / 4; i += 256) {
        int m = m0 + (i * 4) / 128;
        float4 v = make_float4(0.f, 0.f, 0.f, 0.f);
        if (m < B) v = *(const float4*)&ctx[(size_t)m0 * 128 + i * 4];
        ((float4*)Cs)[i] = v;
    }
    __syncthreads();
    int w = tid >> 5, lane = tid & 31;
    float acc[8][4];
#pragma unroll
    for (int i = 0; i < 8; i++)
#pragma unroll
        for (int u = 0; u < 4; u++) acc[i][u] = 0.f;

    for (int k0 = 0; k0 < 128; k0 += 16) {
        for (int i = tid; i < 16 * 128; i += 256) {
            int kk = i & 15, u = i >> 4;
            Wc[kk][u] = Cw[(size_t)u * 128 + k0 + kk];
        }
        __syncthreads();
#pragma unroll
        for (int kk = 0; kk < 16; kk++) {
            float wv[4];
#pragma unroll
            for (int u = 0; u < 4; u++) wv[u] = Wc[kk][lane * 4 + u];
#pragma unroll
            for (int i = 0; i < 8; i++) {
                float a = Cs[w * 8 + i][k0 + kk];
#pragma unroll
                for (int u = 0; u < 4; u++) acc[i][u] += a * wv[u];
            }
        }
        __syncthreads();
    }
#pragma unroll
    for (int i = 0; i < 8; i++) {
        int m = m0 + w * 8 + i;
        if (m >= B) continue;
#pragma unroll
        for (int u = 0; u < 4; u++) {
            int ug = lane * 4 + u;
            outp[(size_t)m * 128 + ug] = acc[i][u] + cb[ug];
        }
    }
}

// ---------------------------------------------------------------------------
// tensor-core helpers
// ---------------------------------------------------------------------------
__device__ __forceinline__ void mma_bf16(float* c, const uint32_t* a, uint32_t b0, uint32_t b1) {
    asm volatile(
        "mma.sync.aligned.m16n8k16.row.col.f32.bf16.bf16.f32 "
        "{%0,%1,%2,%3}, {%4,%5,%6,%7}, {%8,%9}, {%0,%1,%2,%3};\n"
        : "+f"(c[0]), "+f"(c[1]), "+f"(c[2]), "+f"(c[3])
        : "r"(a[0]), "r"(a[1]), "r"(a[2]), "r"(a[3]), "r"(b0), "r"(b1));
}

__device__ __forceinline__ void ldsm_x4(uint32_t* r, const __nv_bfloat16* base,
                                        int row, int col, int lane) {
    int g = lane >> 3, rr = lane & 7;
    const __nv_bfloat16* p = base + (size_t)(row + (g & 1) * 8 + rr) * STR + col + (g >> 1) * 8;
    uint32_t addr = (uint32_t)__cvta_generic_to_shared(p);
    asm volatile("ldmatrix.sync.aligned.m8n8.x4.shared.b16 {%0,%1,%2,%3}, [%4];"
                 : "=r"(r[0]), "=r"(r[1]), "=r"(r[2]), "=r"(r[3]) : "r"(addr));
}

__device__ __forceinline__ void ldsm_x2(uint32_t* r, const __nv_bfloat16* base,
                                        int row, int col, int lane) {
    int l = lane & 15;
    int g = l >> 3, rr = l & 7;
    const __nv_bfloat16* p = base + (size_t)(row + rr) * STR + col + g * 8;
    uint32_t addr = (uint32_t)__cvta_generic_to_shared(p);
    asm volatile("ldmatrix.sync.aligned.m8n8.x2.shared.b16 {%0,%1}, [%2];"
                 : "=r"(r[0]), "=r"(r[1]) : "r"(addr));
}

template<bool ALT>
__device__ __forceinline__ void mma_all(float (&accA)[2][6][4], float (&accH)[2][2][4],
                                        uint32_t a[2][4], uint32_t b[6][2]) {
#pragma unroll
    for (int mf = 0; mf < 2; mf++)
#pragma unroll
        for (int f = 0; f < 6; f++) {
            float* c = (ALT && f >= 4) ? accH[mf][f - 4] : accA[mf][f];
            mma_bf16(c, a[mf], b[f][0], b[f][1]);
        }
}

// One GEMM phase: acc += split_bf16(X[128 x K]) @ split_bf16(W[96 x K])^T
// GEMM cols organized as 12 n-frags of 8; warp nw owns frags {2f+nw};
// frag index f>=4 <=> plane 2 (candidate-gate) for both warps (uniform).
template<bool ALT>
__device__ __forceinline__ void gemm_phase(
    const float* __restrict__ X, int ldx, int K,
    const __nv_bfloat16* __restrict__ wHi, const __nv_bfloat16* __restrict__ wLo, int ldwp,
    int m0, int n0, int B,
    __nv_bfloat16* Ahi, __nv_bfloat16* Alo, __nv_bfloat16* Whi, __nv_bfloat16* Wlo,
    float (&accA)[2][6][4], float (&accH)[2][2][4]) {
    const int tid = threadIdx.x;
    const int lane = tid & 31;
    const int w = tid >> 5;
    const int mw = w >> 1;
    const int nw = w & 1;

    for (int k0 = 0; k0 < K; k0 += 64) {
        const int kLen = min(64, K - k0);
        __syncthreads();
        // stage W (packed bf16, zero-padded at pack time): 96 rows x 64 cols
        for (int i = tid; i < 768; i += 256) {
            int r = i >> 3, q = i & 7;
            int grow = ((r >> 5) << 8) + n0 + (r & 31);
            size_t so = (size_t)grow * ldwp + k0 + q * 8;
            *(uint4*)(Whi + (size_t)r * STR + q * 8) = *(const uint4*)(wHi + so);
            *(uint4*)(Wlo + (size_t)r * STR + q * 8) = *(const uint4*)(wLo + so);
        }
        // stage A with on-the-fly hi/lo split
        if (kLen == 64 && (ldx & 3) == 0) {
            for (int i = tid; i < 2048; i += 256) {
                int r = i >> 4, c = (i & 15) * 4;
                int m = m0 + r;
                float4 v = make_float4(0.f, 0.f, 0.f, 0.f);
                if (m < B) v = *(const float4*)(X + (size_t)m * ldx + k0 + c);
                __nv_bfloat162 h0 = __floats2bfloat162_rn(v.x, v.y);
                __nv_bfloat162 h1 = __floats2bfloat162_rn(v.z, v.w);
                *(__nv_bfloat162*)(Ahi + (size_t)r * STR + c)     = h0;
                *(__nv_bfloat162*)(Ahi + (size_t)r * STR + c + 2) = h1;
                __nv_bfloat162 l0 = __floats2bfloat162_rn(v.x - __bfloat162float(h0.x),
                                                          v.y - __bfloat162float(h0.y));
                __nv_bfloat162 l1 = __floats2bfloat162_rn(v.z - __bfloat162float(h1.x),
                                                          v.w - __bfloat162float(h1.y));
                *(__nv_bfloat162*)(Alo + (size_t)r * STR + c)     = l0;
                *(__nv_bfloat162*)(Alo + (size_t)r * STR + c + 2) = l1;
            }
        } else {
            for (int i = tid; i < 8192; i += 256) {
                int r = i >> 6, c = i & 63;
                int m = m0 + r;
                float x = (m < B && c < kLen) ? X[(size_t)m * ldx + k0 + c] : 0.f;
                __nv_bfloat16 h = __float2bfloat16(x);
                Ahi[(size_t)r * STR + c] = h;
                Alo[(size_t)r * STR + c] = __float2bfloat16(x - __bfloat162float(h));
            }
        }
        __syncthreads();
#pragma unroll
        for (int ks = 0; ks < 4; ks++) {
            uint32_t ah[2][4], al[2][4], b[6][2];
            ldsm_x4(ah[0], Ahi, mw * 32,      ks * 16, lane);
            ldsm_x4(ah[1], Ahi, mw * 32 + 16, ks * 16, lane);
            ldsm_x4(al[0], Alo, mw * 32,      ks * 16, lane);
            ldsm_x4(al[1], Alo, mw * 32 + 16, ks * 16, lane);
#pragma unroll
            for (int f = 0; f < 6; f++) ldsm_x2(b[f], Whi, (f * 2 + nw) * 8, ks * 16, lane);
            mma_all<ALT>(accA, accH, ah, b);   // hi*hi
            mma_all<ALT>(accA, accH, al, b);   // lo*hi
#pragma unroll
            for (int f = 0; f < 6; f++) ldsm_x2(b[f], Wlo, (f * 2 + nw) * 8, ks * 16, lane);
            mma_all<ALT>(accA, accH, ah, b);   // hi*lo
        }
    }
}

// ---------------------------------------------------------------------------
// Fused GRU cell (tensor-core). smem: staging tiles unioned with gate buffer.
// ---------------------------------------------------------------------------
#define GRU_SMEM 73728   // max(tiles 64512, gbuf 4*128*36*4 = 73728)

__global__ __launch_bounds__(256) void gru_mma_kernel(
    const float* __restrict__ X1, int ld1, int k1,
    const float* __restrict__ X2, int ld2, int k2,
    const float* __restrict__ Hin, int do_hidden,
    const __nv_bfloat16* __restrict__ wpack,
    long wih_off, int wih_ldp, long whh_off,
    const float* __restrict__ bih, const float* __restrict__ bhh,
    float* __restrict__ Hout, int B) {
    extern __shared__ char sm_[];
    __nv_bfloat16* Ahi = (__nv_bfloat16*)sm_;
    __nv_bfloat16* Alo = Ahi + 128 * STR;
    __nv_bfloat16* Whi = Alo + 128 * STR;
    __nv_bfloat16* Wlo = Whi + 96 * STR;
    float* gbuf = (float*)sm_;

    const int tid = threadIdx.x;
    const int lane = tid & 31;
    const int w = tid >> 5;
    const int mw = w >> 1;
    const int nw = w & 1;
    const int m0 = blockIdx.x * 128;
    const int n0 = blockIdx.y * 32;

    float accA[2][6][4];
    float accH[2][2][4];
#pragma unroll
    for (int mf = 0; mf < 2; mf++) {
#pragma unroll
        for (int f = 0; f < 6; f++)
#pragma unroll
            for (int u = 0; u < 4; u++) accA[mf][f][u] = 0.f;
#pragma unroll
        for (int f = 0; f < 2; f++)
#pragma unroll
            for (int u = 0; u < 4; u++) accH[mf][f][u] = 0.f;
    }

    gemm_phase<false>(X1, ld1, k1, wpack + wih_off, wpack + WTOT + wih_off, wih_ldp,
                      m0, n0, B, Ahi, Alo, Whi, Wlo, accA, accH);
    if (k2 > 0)
        gemm_phase<false>(X2, ld2, k2, wpack + wih_off + k1, wpack + WTOT + wih_off + k1, wih_ldp,
                          m0, n0, B, Ahi, Alo, Whi, Wlo, accA, accH);
    if (do_hidden)
        gemm_phase<true>(Hin, 256, 256, wpack + whh_off, wpack + WTOT + whh_off, 256,
                         m0, n0, B, Ahi, Alo, Whi, Wlo, accA, accH);

    // ---- scatter accumulators to gate buffer ----
    __syncthreads();
    {
        int r0 = mw * 32 + (lane >> 2);
        int cl = (lane & 3) * 2;
#pragma unroll
        for (int mf = 0; mf < 2; mf++) {
#pragma unroll
            for (int f = 0; f < 6; f++) {
                int gf = f * 2 + nw;
                int p = gf >> 2;
                int col = ((gf * 8) & 31) + cl;
                int rr = r0 + mf * 16;
                float* g0 = gbuf + ((size_t)(p * 128 + rr)) * 36 + col;
                g0[0] = accA[mf][f][0]; g0[1] = accA[mf][f][1];
                g0[8 * 36] = accA[mf][f][2]; g0[8 * 36 + 1] = accA[mf][f][3];
                if (f >= 4) {
                    float* g1 = gbuf + ((size_t)(3 * 128 + rr)) * 36 + col;
                    g1[0] = accH[mf][f - 4][0]; g1[1] = accH[mf][f - 4][1];
                    g1[8 * 36] = accH[mf][f - 4][2]; g1[8 * 36 + 1] = accH[mf][f - 4][3];
                }
            }
        }
    }
    __syncthreads();

    // ---- gate epilogue ----
    {
        int row = tid >> 1;
        int m = m0 + row;
        int cbase = (tid & 1) * 16;
#pragma unroll
        for (int c4 = 0; c4 < 4; c4++) {
            int col = cbase + c4 * 4;
            int jg = n0 + col;
            float4 gr = *(float4*)(gbuf + (size_t)(0 * 128 + row) * 36 + col);
            float4 gz = *(float4*)(gbuf + (size_t)(1 * 128 + row) * 36 + col);
            float4 gi = *(float4*)(gbuf + (size_t)(2 * 128 + row) * 36 + col);
            float4 gh = *(float4*)(gbuf + (size_t)(3 * 128 + row) * 36 + col);
            float4 hp = make_float4(0.f, 0.f, 0.f, 0.f);
            if (m < B) hp = *(const float4*)(Hin + (size_t)m * 256 + jg);
            float4 br1 = *(const float4*)(bih + jg);
            float4 br2 = *(const float4*)(bhh + jg);
            float4 bz1 = *(const float4*)(bih + 256 + jg);
            float4 bz2 = *(const float4*)(bhh + 256 + jg);
            float4 bg1 = *(const float4*)(bih + 512 + jg);
            float4 bg2 = *(const float4*)(bhh + 512 + jg);
            float4 o;
#define GATE(OUT, GR, GZ, GI, GH, HP, BR1, BR2, BZ1, BZ2, BG1, BG2)                 \
            {                                                                        \
                float r_ = 1.f / (1.f + expf(-((GR) + (BR1) + (BR2))));              \
                float z_ = 1.f / (1.f + expf(-((GZ) + (BZ1) + (BZ2))));              \
                float n_ = tanhf((GI) + (BG1) + r_ * ((GH) + (BG2)));                \
                OUT = (1.f - z_) * n_ + z_ * (HP);                                   \
            }
            GATE(o.x, gr.x, gz.x, gi.x, gh.x, hp.x, br1.x, br2.x, bz1.x, bz2.x, bg1.x, bg2.x);
            GATE(o.y, gr.y, gz.y, gi.y, gh.y, hp.y, br1.y, br2.y, bz1.y, bz2.y, bg1.y, bg2.y);
            GATE(o.z, gr.z, gz.z, gi.z, gh.z, hp.z, br1.z, br2.z, bz1.z, bz2.z, bg1.z, bg2.z);
            GATE(o.w, gr.w, gz.w, gi.w, gh.w, hp.w, br1.w, br2.w, bz1.w, bz2.w, bg1.w, bg2.w);
#undef GATE
            if (m < B) *(float4*)(Hout + (size_t)m * 256 + jg) = o;
        }
    }
}

// ---------------------------------------------------------------------------
// projection heads (fp32, unchanged)
// ---------------------------------------------------------------------------
#define PROJ_SMEM ((64 * 256 + 64 * 196 + 16 * 192) * 4)

__global__ __launch_bounds__(256) void proj_kernel(
    const float* __restrict__ H, const float* __restrict__ P1, const float* __restrict__ p1b,
    const float* __restrict__ P2, const float* __restrict__ p2b,
    const float* __restrict__ A1, const float* __restrict__ a1b,
    const float* __restrict__ A2, const float* __restrict__ a2b,
    float* __restrict__ out, float* __restrict__ dyn, int B, int tstep) {
    extern __shared__ float ps[];
    float* Hs = ps;
    float* D1 = ps + 64 * 256;
    float* Wsh = D1 + 64 * 196;
    int tid = threadIdx.x;
    int m0 = blockIdx.x * 64;

    for (int i = tid; i < 64 * 256 / 4; i += 256) {
        int m = m0 + (i * 4) / 256;
        float4 v = make_float4(0.f, 0.f, 0.f, 0.f);
        if (m < B) v = *(const float4*)&H[(size_t)m0 * 256 + i * 4];
        ((float4*)Hs)[i] = v;
    }
    __syncthreads();

    int w = tid >> 5, lane = tid & 31;
    float acc[8][6];
#pragma unroll
    for (int i = 0; i < 8; i++)
#pragma unroll
        for (int u = 0; u < 6; u++) acc[i][u] = 0.f;

    for (int k0 = 0; k0 < 256; k0 += 16) {
        for (int i = tid; i < 16 * 192; i += 256) {
            int kk = i & 15, u = i >> 4;
            Wsh[kk * 192 + u] = (u < 128) ? P1[(size_t)u * 256 + k0 + kk]
                                          : A1[(size_t)(u - 128) * 256 + k0 + kk];
        }
        __syncthreads();
#pragma unroll
        for (int kk = 0; kk < 16; kk++) {
            float wv[6];
#pragma unroll
            for (int u = 0; u < 6; u++) wv[u] = Wsh[kk * 192 + lane * 6 + u];
#pragma unroll
            for (int i = 0; i < 8; i++) {
                float a = Hs[(w * 8 + i) * 256 + k0 + kk];
#pragma unroll
                for (int u = 0; u < 6; u++) acc[i][u] += a * wv[u];
            }
        }
        __syncthreads();
    }
#pragma unroll
    for (int i = 0; i < 8; i++) {
        int s = w * 8 + i;
#pragma unroll
        for (int u = 0; u < 6; u++) {
            int uu = lane * 6 + u;
            float b = (uu < 128) ? p1b[uu] : a1b[uu - 128];
            float v = acc[i][u] + b;
            D1[s * 196 + uu] = v * normcdff(v);
        }
    }
    __syncthreads();

    {
        int s = tid >> 2, o = tid & 3;
        float a = p2b[o];
        for (int k = 0; k < 128; k++) a += D1[s * 196 + k] * P2[(size_t)o * 128 + k];
        int m = m0 + s;
        if (m < B) {
            out[(size_t)m * 48 + tstep * 4 + o] = a;
            dyn[(size_t)m * 6 + (o < 2 ? o : o + 2)] = a;
        }
    }
    if (tid < 128) {
        int s = tid >> 1, o = tid & 1;
        float a = a2b[o];
        for (int k = 0; k < 64; k++) a += D1[s * 196 + 128 + k] * A2[(size_t)o * 64 + k];
        int m = m0 + s;
        if (m < B) dyn[(size_t)m * 6 + 2 + o] = a;
    }
}

// ---------------------------------------------------------------------------
extern "C" void kernel_launch(void* const* d_in, const int* in_sizes, int n_in,
                              void* d_out, int out_size) {
    const float* ctx      = (const float*)d_in[0];
    const float* obs_traj = (const float*)d_in[1];
    const float* obs_Me   = (const float*)d_in[2];
    const float* Wih0 = (const float*)d_in[3];
    const float* Whh0 = (const float*)d_in[4];
    const float* bih0 = (const float*)d_in[5];
    const float* bhh0 = (const float*)d_in[6];
    const float* Wih1 = (const float*)d_in[7];
    const float* Whh1 = (const float*)d_in[8];
    const float* bih1 = (const float*)d_in[9];
    const float* bhh1 = (const float*)d_in[10];
    const float* Wihs = (const float*)d_in[11];
    const float* Whhs = (const float*)d_in[12];
    const float* bihs = (const float*)d_in[13];
    const float* bhhs = (const float*)d_in[14];
    const float* P1  = (const float*)d_in[15];
    const float* p1b = (const float*)d_in[16];
    const float* P2  = (const float*)d_in[17];
    const float* p2b = (const float*)d_in[18];
    const float* A1  = (const float*)d_in[19];
    const float* a1b = (const float*)d_in[20];
    const float* A2  = (const float*)d_in[21];
    const float* a2b = (const float*)d_in[22];
    const float* Cw  = (const float*)d_in[23];
    const float* cb  = (const float*)d_in[24];
    float* out = (float*)d_out;

    int B = in_sizes[0] / CTXD;
    if (B > BMAX) B = BMAX;
    int T = in_sizes[1] / (2 * B);
    int TS = T - 1;

    float *h0a, *h0b, *h1a, *h1b, *obsin, *ctxp, *dynA, *dynB;
    __nv_bfloat16* wpk;
    cudaGetSymbolAddress((void**)&h0a, g_h0a);
    cudaGetSymbolAddress((void**)&h0b, g_h0b);
    cudaGetSymbolAddress((void**)&h1a, g_h1a);
    cudaGetSymbolAddress((void**)&h1b, g_h1b);
    cudaGetSymbolAddress((void**)&obsin, g_obsin);
    cudaGetSymbolAddress((void**)&ctxp, g_ctxp);
    cudaGetSymbolAddress((void**)&dynA, g_dynA);
    cudaGetSymbolAddress((void**)&dynB, g_dynB);
    cudaGetSymbolAddress((void**)&wpk, g_wpack);

    cudaFuncSetAttribute(proj_kernel, cudaFuncAttributeMaxDynamicSharedMemorySize, PROJ_SMEM);
    cudaFuncSetAttribute(gru_mma_kernel, cudaFuncAttributeMaxDynamicSharedMemorySize, GRU_SMEM);

    // pack weights -> bf16 hi/lo
    pack_kernel<<<(768 * 64 + 255) / 256, 256>>>(Wih0, 6, 64, O_WIH0, wpk);
    pack_kernel<<<(768 * 256 + 255) / 256, 256>>>(Whh0, 256, 256, O_WHH0, wpk);
    pack_kernel<<<(768 * 256 + 255) / 256, 256>>>(Wih1, 256, 256, O_WIH1, wpk);
    pack_kernel<<<(768 * 256 + 255) / 256, 256>>>(Whh1, 256, 256, O_WHH1, wpk);
    pack_kernel<<<(768 * 192 + 255) / 256, 256>>>(Wihs, 134, 192, O_WIHS, wpk);
    pack_kernel<<<(768 * 256 + 255) / 256, 256>>>(Whhs, 256, 256, O_WHHS, wpk);

    zero_kernel<<<264, 256>>>(h0a, B * HDIM);
    zero_kernel<<<264, 256>>>(h1a, B * HDIM);
    prep_kernel<<<(B + 255) / 256, 256>>>(obs_traj, obs_Me, obsin, dynA, B, T);
    ctx_kernel<<<(B + 63) / 64, 256>>>(ctx, Cw, cb, ctxp, B);

    dim3 cgrid((B + 127) / 128, 8);

    // encoder
    float *h0i = h0a, *h0o = h0b, *h1i = h1a, *h1o = h1b;
    for (int t = 0; t < TS; t++) {
        gru_mma_kernel<<<cgrid, 256, GRU_SMEM>>>(obsin + (size_t)t * B * 6, 6, 6,
                                                 nullptr, 0, 0,
                                                 h0i, (t > 0) ? 1 : 0,
                                                 wpk, O_WIH0, 64, O_WHH0,
                                                 bih0, bhh0, h0o, B);
        gru_mma_kernel<<<cgrid, 256, GRU_SMEM>>>(h0o, 256, 256,
                                                 nullptr, 0, 0,
                                                 h1i, (t > 0) ? 1 : 0,
                                                 wpk, O_WIH1, 256, O_WHH1,
                                                 bih1, bhh1, h1o, B);
        float* t0 = h0i; h0i = h0o; h0o = t0;
        float* t1 = h1i; h1i = h1o; h1o = t1;
    }

    // decoder
    float* dhi = h1i;
    float* dho = h1o;
    float* dyi = dynA;
    float* dyo = dynB;
    for (int s = 0; s < PRED; s++) {
        gru_mma_kernel<<<cgrid, 256, GRU_SMEM>>>(ctxp, 128, 128,
                                                 dyi, 6, 6,
                                                 dhi, 1,
                                                 wpk, O_WIHS, 192, O_WHHS,
                                                 bihs, bhhs, dho, B);
        proj_kernel<<<(B + 63) / 64, 256, PROJ_SMEM>>>(dho, P1, p1b, P2, p2b,
                                                       A1, a1b, A2, a2b,
                                                       out, dyo, B, s);
        float* td = dhi; dhi = dho; dho = td;
        float* ty_ = dyi; dyi = dyo; dyo = ty_;
    }
}

// round 4
// speedup vs baseline: 3.2739x; 1.2222x over previous
#include <cuda_runtime.h>
#include <cuda_bf16.h>
#include <math.h>
#include <stdint.h>

// ---------------------------------------------------------------------------
// DirectRegressionHead: 2-layer GRU encoder (7 steps) + 12-step GRU decoder.
// B=32768, H=256, CTX=128, PRED=12.
// GRU/proj GEMMs: bf16x3 split-precision mma.sync.m16n8k16, fp32 accumulate.
// Decoder ctx-GEMM hoisted; K=6 inputs folded into fp32 epilogue.
// ---------------------------------------------------------------------------

#define BMAX 32768
#define HDIM 256
#define CTXD 128
#define PRED 12
#define STR 72            // smem tile k-stride in bf16 (64 + 8 pad)

// packed weight layout (bf16 elements, hi plane; lo plane at +WTOT)
#define O_WHH0 0L          // 768 x 256
#define O_WIH1 196608L     // 768 x 256
#define O_WHH1 393216L     // 768 x 256
#define O_WHHS 589824L     // 768 x 256
#define O_WCTX 786432L     // 768 x 128  (Wihs cols 0..127)
#define O_PA   884736L     // 192 x 256  (P1 rows 0..127, A1 rows 128..191)
#define WTOT   933888L

// --- static device scratch ---
__device__ float g_h0a[BMAX * HDIM];
__device__ float g_h0b[BMAX * HDIM];
__device__ float g_h1a[BMAX * HDIM];
__device__ float g_h1b[BMAX * HDIM];
__device__ float g_obsin[8 * BMAX * 6];
__device__ float g_ctxp[BMAX * CTXD];
__device__ float g_dynA[BMAX * 6];
__device__ float g_dynB[BMAX * 6];
__device__ float g_gictx[BMAX * 768];     // hoisted ctx input-gates
__device__ float g_wdyn0[768 * 8];        // Wih0 (K=6, padded 8), fp32
__device__ float g_wdynS[768 * 8];        // Wihs cols 128..133, fp32
__device__ __nv_bfloat16 g_wpack[2 * WTOT];

// ---------------------------------------------------------------------------
__global__ void zero_kernel(float* __restrict__ p, int n) {
    int stride = gridDim.x * blockDim.x;
    for (int i = blockIdx.x * blockDim.x + threadIdx.x; i * 4 < n; i += stride)
        ((float4*)p)[i] = make_float4(0.f, 0.f, 0.f, 0.f);
}

// pack [rows, K] slice of src (row stride ld, col offset koff) -> hi/lo bf16
__global__ void pack_kernel(const float* __restrict__ W, int rows, int ld, int koff,
                            int K, int Kpad, long dst, __nv_bfloat16* __restrict__ wp) {
    int i = blockIdx.x * blockDim.x + threadIdx.x;
    if (i >= rows * Kpad) return;
    int r = i / Kpad, k = i - r * Kpad;
    float v = (k < K) ? W[(size_t)r * ld + koff + k] : 0.f;
    __nv_bfloat16 h = __float2bfloat16(v);
    wp[dst + i] = h;
    wp[WTOT + dst + i] = __float2bfloat16(v - __bfloat162float(h));
}

// compact fp32 dyn weights: dst[r*8+q] = src[r*ld + koff + q] (q<6)
__global__ void wdyn_pack_kernel(const float* __restrict__ src, int ld, int koff,
                                 float* __restrict__ dst) {
    int i = blockIdx.x * blockDim.x + threadIdx.x;
    if (i >= 768 * 8) return;
    int r = i >> 3, q = i & 7;
    dst[i] = (q < 6) ? src[(size_t)r * ld + koff + q] : 0.f;
}

// ---------------------------------------------------------------------------
__global__ void prep_kernel(const float* __restrict__ traj,
                            const float* __restrict__ me,
                            float* __restrict__ obsin,
                            float* __restrict__ dyn, int B, int T) {
    int b = blockIdx.x * blockDim.x + threadIdx.x;
    if (b >= B) return;
    float vx[8], vy[8], mx[8], my_[8];
    int TS = T - 1;
    if (TS > 8) TS = 8;
    for (int t = 0; t < TS; t++) {
        vx[t]  = traj[((size_t)(t + 1) * B + b) * 2 + 0] - traj[((size_t)t * B + b) * 2 + 0];
        vy[t]  = traj[((size_t)(t + 1) * B + b) * 2 + 1] - traj[((size_t)t * B + b) * 2 + 1];
        mx[t]  = me[((size_t)(t + 1) * B + b) * 2 + 0] - me[((size_t)t * B + b) * 2 + 0];
        my_[t] = me[((size_t)(t + 1) * B + b) * 2 + 1] - me[((size_t)t * B + b) * 2 + 1];
    }
    for (int t = 0; t < TS; t++) {
        int ta = (t == 0) ? 1 : t;
        float ax = vx[ta] - vx[ta - 1];
        float ay = vy[ta] - vy[ta - 1];
        float* o = obsin + ((size_t)t * B + b) * 6;
        o[0] = vx[t]; o[1] = vy[t];
        o[2] = mx[t]; o[3] = my_[t];
        o[4] = ax;    o[5] = ay;
    }
    dyn[(size_t)b * 6 + 0] = vx[TS - 1];
    dyn[(size_t)b * 6 + 1] = vy[TS - 1];
    dyn[(size_t)b * 6 + 2] = vx[TS - 1] - vx[TS - 2];
    dyn[(size_t)b * 6 + 3] = vy[TS - 1] - vy[TS - 2];
    dyn[(size_t)b * 6 + 4] = mx[TS - 1];
    dyn[(size_t)b * 6 + 5] = my_[TS - 1];
}

// ---------------------------------------------------------------------------
__global__ __launch_bounds__(256) void ctx_kernel(const float* __restrict__ ctx,
                                                  const float* __restrict__ Cw,
                                                  const float* __restrict__ cb,
                                                  float* __restrict__ outp, int B) {
    __shared__ float Cs[64][128];
    __shared__ float Wc[16][128];
    int tid = threadIdx.x;
    int m0 = blockIdx.x * 64;
    for (int i = tid; i < 64 * 128 / 4; i += 256) {
        int m = m0 + (i * 4) / 128;
        float4 v = make_float4(0.f, 0.f, 0.f, 0.f);
        if (m < B) v = *(const float4*)&ctx[(size_t)m0 * 128 + i * 4];
        ((float4*)Cs)[i] = v;
    }
    __syncthreads();
    int w = tid >> 5, lane = tid & 31;
    float acc[8][4];
#pragma unroll
    for (int i = 0; i < 8; i++)
#pragma unroll
        for (int u = 0; u < 4; u++) acc[i][u] = 0.f;

    for (int k0 = 0; k0 < 128; k0 += 16) {
        for (int i = tid; i < 16 * 128; i += 256) {
            int kk = i & 15, u = i >> 4;
            Wc[kk][u] = Cw[(size_t)u * 128 + k0 + kk];
        }
        __syncthreads();
#pragma unroll
        for (int kk = 0; kk < 16; kk++) {
            float wv[4];
#pragma unroll
            for (int u = 0; u < 4; u++) wv[u] = Wc[kk][lane * 4 + u];
#pragma unroll
            for (int i = 0; i < 8; i++) {
                float a = Cs[w * 8 + i][k0 + kk];
#pragma unroll
                for (int u = 0; u < 4; u++) acc[i][u] += a * wv[u];
            }
        }
        __syncthreads();
    }
#pragma unroll
    for (int i = 0; i < 8; i++) {
        int m = m0 + w * 8 + i;
        if (m >= B) continue;
#pragma unroll
        for (int u = 0; u < 4; u++) {
            int ug = lane * 4 + u;
            outp[(size_t)m * 128 + ug] = acc[i][u] + cb[ug];
        }
    }
}

// ---------------------------------------------------------------------------
// tensor-core helpers
// ---------------------------------------------------------------------------
__device__ __forceinline__ void mma_bf16(float* c, const uint32_t* a, uint32_t b0, uint32_t b1) {
    asm volatile(
        "mma.sync.aligned.m16n8k16.row.col.f32.bf16.bf16.f32 "
        "{%0,%1,%2,%3}, {%4,%5,%6,%7}, {%8,%9}, {%0,%1,%2,%3};\n"
        : "+f"(c[0]), "+f"(c[1]), "+f"(c[2]), "+f"(c[3])
        : "r"(a[0]), "r"(a[1]), "r"(a[2]), "r"(a[3]), "r"(b0), "r"(b1));
}

__device__ __forceinline__ void ldsm_x4(uint32_t* r, const __nv_bfloat16* base,
                                        int row, int col, int lane) {
    int g = lane >> 3, rr = lane & 7;
    const __nv_bfloat16* p = base + (size_t)(row + (g & 1) * 8 + rr) * STR + col + (g >> 1) * 8;
    uint32_t addr = (uint32_t)__cvta_generic_to_shared(p);
    asm volatile("ldmatrix.sync.aligned.m8n8.x4.shared.b16 {%0,%1,%2,%3}, [%4];"
                 : "=r"(r[0]), "=r"(r[1]), "=r"(r[2]), "=r"(r[3]) : "r"(addr));
}

__device__ __forceinline__ void ldsm_x2(uint32_t* r, const __nv_bfloat16* base,
                                        int row, int col, int lane) {
    int l = lane & 15;
    int g = l >> 3, rr = l & 7;
    const __nv_bfloat16* p = base + (size_t)(row + rr) * STR + col + g * 8;
    uint32_t addr = (uint32_t)__cvta_generic_to_shared(p);
    asm volatile("ldmatrix.sync.aligned.m8n8.x2.shared.b16 {%0,%1}, [%2];"
                 : "=r"(r[0]), "=r"(r[1]) : "r"(addr));
}

template<bool ALT>
__device__ __forceinline__ void mma_all(float (&accA)[2][6][4], float (&accH)[2][2][4],
                                        uint32_t a[2][4], uint32_t b[6][2]) {
#pragma unroll
    for (int mf = 0; mf < 2; mf++)
#pragma unroll
        for (int f = 0; f < 6; f++) {
            float* c = (ALT && f >= 4) ? accH[mf][f - 4] : accA[mf][f];
            mma_bf16(c, a[mf], b[f][0], b[f][1]);
        }
}

// acc += split_bf16(X[128 x K]) @ split_bf16(W[96 x K])^T
// K must be a multiple of 64; X row stride ldx multiple of 4.
// Weight row mapping: grow = (r>>5)*plane_stride + n0 + (r&31).
template<bool ALT>
__device__ __forceinline__ void gemm_phase(
    const float* __restrict__ X, int ldx, int K,
    const __nv_bfloat16* __restrict__ wHi, const __nv_bfloat16* __restrict__ wLo,
    int ldwp, int plane_stride,
    int m0, int n0, int B,
    __nv_bfloat16* Ahi, __nv_bfloat16* Alo, __nv_bfloat16* Whi, __nv_bfloat16* Wlo,
    float (&accA)[2][6][4], float (&accH)[2][2][4]) {
    const int tid = threadIdx.x;
    const int lane = tid & 31;
    const int w = tid >> 5;
    const int mw = w >> 1;
    const int nw = w & 1;

    for (int k0 = 0; k0 < K; k0 += 64) {
        __syncthreads();
        // stage W: 96 rows x 64 cols (hi + lo)
        for (int i = tid; i < 768; i += 256) {
            int r = i >> 3, q = i & 7;
            int grow = (r >> 5) * plane_stride + n0 + (r & 31);
            size_t so = (size_t)grow * ldwp + k0 + q * 8;
            *(uint4*)(Whi + (size_t)r * STR + q * 8) = *(const uint4*)(wHi + so);
            *(uint4*)(Wlo + (size_t)r * STR + q * 8) = *(const uint4*)(wLo + so);
        }
        // stage A with on-the-fly hi/lo split
        for (int i = tid; i < 2048; i += 256) {
            int r = i >> 4, c = (i & 15) * 4;
            int m = m0 + r;
            float4 v = make_float4(0.f, 0.f, 0.f, 0.f);
            if (m < B) v = *(const float4*)(X + (size_t)m * ldx + k0 + c);
            __nv_bfloat162 h0 = __floats2bfloat162_rn(v.x, v.y);
            __nv_bfloat162 h1 = __floats2bfloat162_rn(v.z, v.w);
            *(__nv_bfloat162*)(Ahi + (size_t)r * STR + c)     = h0;
            *(__nv_bfloat162*)(Ahi + (size_t)r * STR + c + 2) = h1;
            __nv_bfloat162 l0 = __floats2bfloat162_rn(v.x - __bfloat162float(h0.x),
                                                      v.y - __bfloat162float(h0.y));
            __nv_bfloat162 l1 = __floats2bfloat162_rn(v.z - __bfloat162float(h1.x),
                                                      v.w - __bfloat162float(h1.y));
            *(__nv_bfloat162*)(Alo + (size_t)r * STR + c)     = l0;
            *(__nv_bfloat162*)(Alo + (size_t)r * STR + c + 2) = l1;
        }
        __syncthreads();
#pragma unroll
        for (int ks = 0; ks < 4; ks++) {
            uint32_t ah[2][4], al[2][4], b[6][2];
            ldsm_x4(ah[0], Ahi, mw * 32,      ks * 16, lane);
            ldsm_x4(ah[1], Ahi, mw * 32 + 16, ks * 16, lane);
            ldsm_x4(al[0], Alo, mw * 32,      ks * 16, lane);
            ldsm_x4(al[1], Alo, mw * 32 + 16, ks * 16, lane);
#pragma unroll
            for (int f = 0; f < 6; f++) ldsm_x2(b[f], Whi, (f * 2 + nw) * 8, ks * 16, lane);
            mma_all<ALT>(accA, accH, ah, b);   // hi*hi
            mma_all<ALT>(accA, accH, al, b);   // lo*hi
#pragma unroll
            for (int f = 0; f < 6; f++) ldsm_x2(b[f], Wlo, (f * 2 + nw) * 8, ks * 16, lane);
            mma_all<ALT>(accA, accH, ah, b);   // hi*lo
        }
    }
}

// ---------------------------------------------------------------------------
// Fused GRU cell. smem: staging tiles (64512B) unioned with gbuf (73728B),
// plus dyn-weight cache (3072B) after gbuf.
// mode 0: full gate epilogue; mode 1: store raw input-gates to gi_out.
// ---------------------------------------------------------------------------
#define GRU_SMEM 76800

__global__ __launch_bounds__(256) void gru_mma_kernel(
    const float* __restrict__ X1, int ld1, int k1,
    const float* __restrict__ Hin, int do_hidden,
    const __nv_bfloat16* __restrict__ wpack,
    long wih_off, int wih_ldp, long whh_off,
    const float* __restrict__ gi_ext,
    const float* __restrict__ wdyn,
    const float* __restrict__ xdyn, int ld_dyn,
    const float* __restrict__ bih, const float* __restrict__ bhh,
    float* __restrict__ Hout, float* __restrict__ gi_out, int B, int mode) {
    extern __shared__ char sm_[];
    __nv_bfloat16* Ahi = (__nv_bfloat16*)sm_;
    __nv_bfloat16* Alo = Ahi + 128 * STR;
    __nv_bfloat16* Whi = Alo + 128 * STR;
    __nv_bfloat16* Wlo = Whi + 96 * STR;
    float* gbuf = (float*)sm_;
    float* wd_s = (float*)(sm_ + 73728);

    const int tid = threadIdx.x;
    const int lane = tid & 31;
    const int w = tid >> 5;
    const int mw = w >> 1;
    const int nw = w & 1;
    const int m0 = blockIdx.x * 128;
    const int n0 = blockIdx.y * 32;

    // stage compact dyn weights for this block's 32 cols (3 planes x 32 x 8)
    if (wdyn != nullptr) {
        for (int i = tid; i < 768; i += 256) {
            int rr = i >> 3, q = i & 7;
            int p = rr >> 5, c = rr & 31;
            wd_s[i] = wdyn[((size_t)(p * 256) + n0 + c) * 8 + q];
        }
    }

    float accA[2][6][4];
    float accH[2][2][4];
#pragma unroll
    for (int mf = 0; mf < 2; mf++) {
#pragma unroll
        for (int f = 0; f < 6; f++)
#pragma unroll
            for (int u = 0; u < 4; u++) accA[mf][f][u] = 0.f;
#pragma unroll
        for (int f = 0; f < 2; f++)
#pragma unroll
            for (int u = 0; u < 4; u++) accH[mf][f][u] = 0.f;
    }

    if (X1 != nullptr)
        gemm_phase<false>(X1, ld1, k1, wpack + wih_off, wpack + WTOT + wih_off,
                          wih_ldp, 256, m0, n0, B, Ahi, Alo, Whi, Wlo, accA, accH);
    if (do_hidden)
        gemm_phase<true>(Hin, 256, 256, wpack + whh_off, wpack + WTOT + whh_off,
                         256, 256, m0, n0, B, Ahi, Alo, Whi, Wlo, accA, accH);

    // ---- scatter accumulators to gate buffer ----
    __syncthreads();
    {
        int r0 = mw * 32 + (lane >> 2);
        int cl = (lane & 3) * 2;
#pragma unroll
        for (int mf = 0; mf < 2; mf++) {
#pragma unroll
            for (int f = 0; f < 6; f++) {
                int gf = f * 2 + nw;
                int p = gf >> 2;
                int col = ((gf * 8) & 31) + cl;
                int rr = r0 + mf * 16;
                float* g0 = gbuf + ((size_t)(p * 128 + rr)) * 36 + col;
                g0[0] = accA[mf][f][0]; g0[1] = accA[mf][f][1];
                g0[8 * 36] = accA[mf][f][2]; g0[8 * 36 + 1] = accA[mf][f][3];
                if (f >= 4) {
                    float* g1 = gbuf + ((size_t)(3 * 128 + rr)) * 36 + col;
                    g1[0] = accH[mf][f - 4][0]; g1[1] = accH[mf][f - 4][1];
                    g1[8 * 36] = accH[mf][f - 4][2]; g1[8 * 36 + 1] = accH[mf][f - 4][3];
                }
            }
        }
    }
    __syncthreads();

    if (mode == 1) {
        // store raw input-gate planes (r,z,ig) to gi_out[B,768]
        for (int i = tid; i < 3 * 128 * 32; i += 256) {
            int p = i >> 12; int rem = i & 4095;
            int row = rem >> 5; int col = rem & 31;
            int m = m0 + row;
            if (m < B)
                gi_out[(size_t)m * 768 + p * 256 + n0 + col] =
                    gbuf[(size_t)(p * 128 + row) * 36 + col];
        }
        return;
    }

    // ---- gate epilogue ----
    {
        int row = tid >> 1;
        int m = m0 + row;
        int cbase = (tid & 1) * 16;
        bool valid = (m < B);
        float xd[6];
#pragma unroll
        for (int q = 0; q < 6; q++) xd[q] = 0.f;
        if (wdyn != nullptr && valid) {
#pragma unroll
            for (int q = 0; q < 6; q++) xd[q] = xdyn[(size_t)m * ld_dyn + q];
        }
        float ov[16];
#pragma unroll
        for (int c4 = 0; c4 < 4; c4++) {
            int col = cbase + c4 * 4;
            int jg = n0 + col;
            float grv[4], gzv[4], giv[4], ghv[4], hpv[4];
            *(float4*)grv = *(float4*)(gbuf + (size_t)(0 * 128 + row) * 36 + col);
            *(float4*)gzv = *(float4*)(gbuf + (size_t)(1 * 128 + row) * 36 + col);
            *(float4*)giv = *(float4*)(gbuf + (size_t)(2 * 128 + row) * 36 + col);
            *(float4*)ghv = *(float4*)(gbuf + (size_t)(3 * 128 + row) * 36 + col);
            if (valid) *(float4*)hpv = *(const float4*)(Hin + (size_t)m * 256 + jg);
            else { hpv[0] = hpv[1] = hpv[2] = hpv[3] = 0.f; }
            if (gi_ext != nullptr && valid) {
                float e0[4], e1[4], e2[4];
                *(float4*)e0 = *(const float4*)(gi_ext + (size_t)m * 768 + jg);
                *(float4*)e1 = *(const float4*)(gi_ext + (size_t)m * 768 + 256 + jg);
                *(float4*)e2 = *(const float4*)(gi_ext + (size_t)m * 768 + 512 + jg);
#pragma unroll
                for (int cc = 0; cc < 4; cc++) {
                    grv[cc] += e0[cc]; gzv[cc] += e1[cc]; giv[cc] += e2[cc];
                }
            }
            if (wdyn != nullptr) {
#pragma unroll
                for (int cc = 0; cc < 4; cc++) {
                    int cl_ = col + cc;
                    const float* w0 = wd_s + (0 * 32 + cl_) * 8;
                    const float* w1 = wd_s + (1 * 32 + cl_) * 8;
                    const float* w2 = wd_s + (2 * 32 + cl_) * 8;
#pragma unroll
                    for (int q = 0; q < 6; q++) {
                        grv[cc] += xd[q] * w0[q];
                        gzv[cc] += xd[q] * w1[q];
                        giv[cc] += xd[q] * w2[q];
                    }
                }
            }
#pragma unroll
            for (int cc = 0; cc < 4; cc++) {
                int j = jg + cc;
                float r_ = 1.f / (1.f + expf(-(grv[cc] + bih[j] + bhh[j])));
                float z_ = 1.f / (1.f + expf(-(gzv[cc] + bih[256 + j] + bhh[256 + j])));
                float n_ = tanhf(giv[cc] + bih[512 + j] + r_ * (ghv[cc] + bhh[512 + j]));
                ov[c4 * 4 + cc] = (1.f - z_) * n_ + z_ * hpv[cc];
            }
        }
        if (valid) {
#pragma unroll
            for (int c4 = 0; c4 < 4; c4++)
                *(float4*)(Hout + (size_t)m * 256 + n0 + cbase + c4 * 4) = *(float4*)(ov + c4 * 4);
        }
    }
}

// ---------------------------------------------------------------------------
// projection heads: stage1 [B,192] = GELU(H @ [P1;A1]^T + b) via bf16x3 mma,
// stage2 tiny fp32 head GEMMs. Block = 128 rows, two 96-col phases.
// ---------------------------------------------------------------------------
#define PROJ_SMEM (64512 + 128 * 196 * 4)   // tiles + D1 = 164864

__device__ __forceinline__ void proj_scatter(float (&accA)[2][6][4], float* D1, int n0,
                                             const float* __restrict__ p1b,
                                             const float* __restrict__ a1b,
                                             int mw, int nw, int lane) {
    int r0 = mw * 32 + (lane >> 2);
    int cl = (lane & 3) * 2;
#pragma unroll
    for (int mf = 0; mf < 2; mf++)
#pragma unroll
        for (int f = 0; f < 6; f++) {
            int gf = f * 2 + nw;
            int colb = n0 + gf * 8 + cl;
            int rr = r0 + mf * 16;
#pragma unroll
            for (int jj = 0; jj < 2; jj++) {
                int col = colb + jj;
                float b = (col < 128) ? p1b[col] : a1b[col - 128];
                float v0 = accA[mf][f][jj] + b;
                float v1 = accA[mf][f][2 + jj] + b;
                D1[(size_t)rr * 196 + col] = v0 * normcdff(v0);
                D1[(size_t)(rr + 8) * 196 + col] = v1 * normcdff(v1);
            }
        }
}

__global__ __launch_bounds__(256) void proj_mma_kernel(
    const float* __restrict__ H,
    const __nv_bfloat16* __restrict__ wpack,
    const float* __restrict__ p1b, const float* __restrict__ a1b,
    const float* __restrict__ P2, const float* __restrict__ p2b,
    const float* __restrict__ A2, const float* __restrict__ a2b,
    float* __restrict__ out, float* __restrict__ dyn, int B, int tstep) {
    extern __shared__ char sm_[];
    __nv_bfloat16* Ahi = (__nv_bfloat16*)sm_;
    __nv_bfloat16* Alo = Ahi + 128 * STR;
    __nv_bfloat16* Whi = Alo + 128 * STR;
    __nv_bfloat16* Wlo = Whi + 96 * STR;
    float* D1 = (float*)(sm_ + 64512);
    float* wsm = (float*)sm_;   // reused after GEMM for head weights

    const int tid = threadIdx.x;
    const int lane = tid & 31;
    const int w = tid >> 5;
    const int mw = w >> 1;
    const int nw = w & 1;
    const int m0 = blockIdx.x * 128;

    float accA[2][6][4];
    float accH[2][2][4];
#pragma unroll
    for (int mf = 0; mf < 2; mf++) {
#pragma unroll
        for (int f = 0; f < 6; f++)
#pragma unroll
            for (int u = 0; u < 4; u++) accA[mf][f][u] = 0.f;
#pragma unroll
        for (int f = 0; f < 2; f++)
#pragma unroll
            for (int u = 0; u < 4; u++) accH[mf][f][u] = 0.f;
    }

    gemm_phase<false>(H, 256, 256, wpack + O_PA, wpack + WTOT + O_PA,
                      256, 32, m0, 0, B, Ahi, Alo, Whi, Wlo, accA, accH);
    proj_scatter(accA, D1, 0, p1b, a1b, mw, nw, lane);
#pragma unroll
    for (int mf = 0; mf < 2; mf++)
#pragma unroll
        for (int f = 0; f < 6; f++)
#pragma unroll
            for (int u = 0; u < 4; u++) accA[mf][f][u] = 0.f;
    gemm_phase<false>(H, 256, 256, wpack + O_PA, wpack + WTOT + O_PA,
                      256, 32, m0, 96, B, Ahi, Alo, Whi, Wlo, accA, accH);
    proj_scatter(accA, D1, 96, p1b, a1b, mw, nw, lane);
    __syncthreads();

    // stage head weights into (now free) tile smem
    for (int i = tid; i < 512; i += 256) wsm[i] = P2[i];
    if (tid < 128) wsm[512 + tid] = A2[tid];
    if (tid < 4) wsm[640 + tid] = p2b[tid];
    if (tid < 2) wsm[644 + tid] = a2b[tid];
    __syncthreads();

    // delta head: 128 rows x 4 outs, K=128
#pragma unroll
    for (int it = 0; it < 2; it++) {
        int idx = tid + it * 256;
        int s = idx >> 2, o = idx & 3;
        float a = wsm[640 + o];
        const float* w2 = wsm + o * 128;
        const float* d = D1 + (size_t)s * 196;
#pragma unroll 8
        for (int k = 0; k < 128; k++) a += d[k] * w2[k];
        int m = m0 + s;
        if (m < B) {
            out[(size_t)m * 48 + tstep * 4 + o] = a;
            dyn[(size_t)m * 6 + (o < 2 ? o : o + 2)] = a;
        }
    }
    // accel head: 128 rows x 2 outs, K=64
    {
        int s = tid >> 1, o = tid & 1;
        float a = wsm[644 + o];
        const float* w2 = wsm + 512 + o * 64;
        const float* d = D1 + (size_t)s * 196 + 128;
#pragma unroll 8
        for (int k = 0; k < 64; k++) a += d[k] * w2[k];
        int m = m0 + s;
        if (m < B) dyn[(size_t)m * 6 + 2 + o] = a;
    }
}

// ---------------------------------------------------------------------------
extern "C" void kernel_launch(void* const* d_in, const int* in_sizes, int n_in,
                              void* d_out, int out_size) {
    const float* ctx      = (const float*)d_in[0];
    const float* obs_traj = (const float*)d_in[1];
    const float* obs_Me   = (const float*)d_in[2];
    const float* Wih0 = (const float*)d_in[3];
    const float* Whh0 = (const float*)d_in[4];
    const float* bih0 = (const float*)d_in[5];
    const float* bhh0 = (const float*)d_in[6];
    const float* Wih1 = (const float*)d_in[7];
    const float* Whh1 = (const float*)d_in[8];
    const float* bih1 = (const float*)d_in[9];
    const float* bhh1 = (const float*)d_in[10];
    const float* Wihs = (const float*)d_in[11];
    const float* Whhs = (const float*)d_in[12];
    const float* bihs = (const float*)d_in[13];
    const float* bhhs = (const float*)d_in[14];
    const float* P1  = (const float*)d_in[15];
    const float* p1b = (const float*)d_in[16];
    const float* P2  = (const float*)d_in[17];
    const float* p2b = (const float*)d_in[18];
    const float* A1  = (const float*)d_in[19];
    const float* a1b = (const float*)d_in[20];
    const float* A2  = (const float*)d_in[21];
    const float* a2b = (const float*)d_in[22];
    const float* Cw  = (const float*)d_in[23];
    const float* cb  = (const float*)d_in[24];
    float* out = (float*)d_out;

    int B = in_sizes[0] / CTXD;
    if (B > BMAX) B = BMAX;
    int T = in_sizes[1] / (2 * B);
    int TS = T - 1;

    float *h0a, *h0b, *h1a, *h1b, *obsin, *ctxp, *dynA, *dynB, *gictx, *wd0, *wdS;
    __nv_bfloat16* wpk;
    cudaGetSymbolAddress((void**)&h0a, g_h0a);
    cudaGetSymbolAddress((void**)&h0b, g_h0b);
    cudaGetSymbolAddress((void**)&h1a, g_h1a);
    cudaGetSymbolAddress((void**)&h1b, g_h1b);
    cudaGetSymbolAddress((void**)&obsin, g_obsin);
    cudaGetSymbolAddress((void**)&ctxp, g_ctxp);
    cudaGetSymbolAddress((void**)&dynA, g_dynA);
    cudaGetSymbolAddress((void**)&dynB, g_dynB);
    cudaGetSymbolAddress((void**)&gictx, g_gictx);
    cudaGetSymbolAddress((void**)&wd0, g_wdyn0);
    cudaGetSymbolAddress((void**)&wdS, g_wdynS);
    cudaGetSymbolAddress((void**)&wpk, g_wpack);

    cudaFuncSetAttribute(gru_mma_kernel, cudaFuncAttributeMaxDynamicSharedMemorySize, GRU_SMEM);
    cudaFuncSetAttribute(proj_mma_kernel, cudaFuncAttributeMaxDynamicSharedMemorySize, PROJ_SMEM);

    // pack weights -> bf16 hi/lo (+ fp32 compact dyn slices)
    pack_kernel<<<768, 256>>>(Whh0, 768, 256, 0, 256, 256, O_WHH0, wpk);
    pack_kernel<<<768, 256>>>(Wih1, 768, 256, 0, 256, 256, O_WIH1, wpk);
    pack_kernel<<<768, 256>>>(Whh1, 768, 256, 0, 256, 256, O_WHH1, wpk);
    pack_kernel<<<768, 256>>>(Whhs, 768, 256, 0, 256, 256, O_WHHS, wpk);
    pack_kernel<<<384, 256>>>(Wihs, 768, 134, 0, 128, 128, O_WCTX, wpk);
    pack_kernel<<<128, 256>>>(P1, 128, 256, 0, 256, 256, O_PA, wpk);
    pack_kernel<<<64, 256>>>(A1, 64, 256, 0, 256, 256, O_PA + 128L * 256, wpk);
    wdyn_pack_kernel<<<24, 256>>>(Wih0, 6, 0, wd0);
    wdyn_pack_kernel<<<24, 256>>>(Wihs, 134, 128, wdS);

    zero_kernel<<<264, 256>>>(h0a, B * HDIM);
    zero_kernel<<<264, 256>>>(h1a, B * HDIM);
    prep_kernel<<<(B + 255) / 256, 256>>>(obs_traj, obs_Me, obsin, dynA, B, T);
    ctx_kernel<<<(B + 63) / 64, 256>>>(ctx, Cw, cb, ctxp, B);

    dim3 cgrid((B + 127) / 128, 8);

    // hoisted decoder ctx input-gates: gi_ctx = ctxp @ Wihs[:, :128].T
    gru_mma_kernel<<<cgrid, 256, GRU_SMEM>>>(ctxp, 128, 128, nullptr, 0,
                                             wpk, O_WCTX, 128, 0L,
                                             nullptr, nullptr, nullptr, 0,
                                             bihs, bhhs, nullptr, gictx, B, 1);

    // encoder
    float *h0i = h0a, *h0o = h0b, *h1i = h1a, *h1o = h1b;
    for (int t = 0; t < TS; t++) {
        gru_mma_kernel<<<cgrid, 256, GRU_SMEM>>>(nullptr, 0, 0,
                                                 h0i, (t > 0) ? 1 : 0,
                                                 wpk, 0L, 0, O_WHH0,
                                                 nullptr, wd0, obsin + (size_t)t * B * 6, 6,
                                                 bih0, bhh0, h0o, nullptr, B, 0);
        gru_mma_kernel<<<cgrid, 256, GRU_SMEM>>>(h0o, 256, 256,
                                                 h1i, (t > 0) ? 1 : 0,
                                                 wpk, O_WIH1, 256, O_WHH1,
                                                 nullptr, nullptr, nullptr, 0,
                                                 bih1, bhh1, h1o, nullptr, B, 0);
        float* t0 = h0i; h0i = h0o; h0o = t0;
        float* t1 = h1i; h1i = h1o; h1o = t1;
    }

    // decoder
    float* dhi = h1i;
    float* dho = h1o;
    float* dyi = dynA;
    float* dyo = dynB;
    for (int s = 0; s < PRED; s++) {
        gru_mma_kernel<<<cgrid, 256, GRU_SMEM>>>(nullptr, 0, 0,
                                                 dhi, 1,
                                                 wpk, 0L, 0, O_WHHS,
                                                 gictx, wdS, dyi, 6,
                                                 bihs, bhhs, dho, nullptr, B, 0);
        proj_mma_kernel<<<(B + 127) / 128, 256, PROJ_SMEM>>>(dho, wpk, p1b, a1b,
                                                             P2, p2b, A2, a2b,
                                                             out, dyo, B, s);
        float* td = dhi; dhi = dho; dho = td;
        float* ty_ = dyi; dyi = dyo; dyo = ty_;
    }
}

// round 5
// speedup vs baseline: 3.2772x; 1.0010x over previous
#include <cuda_runtime.h>
#include <cuda_bf16.h>
#include <math.h>
#include <stdint.h>

// ---------------------------------------------------------------------------
// DirectRegressionHead: 2-layer GRU encoder (7 steps) + 12-step GRU decoder.
// B=32768, H=256, CTX=128, PRED=12.
// GRU/proj GEMMs: bf16x3 split-precision mma.sync.m16n8k16, fp32 accumulate.
// Decoder ctx-GEMM hoisted; K=6 inputs folded into fp32 epilogue.
// ---------------------------------------------------------------------------

#define BMAX 32768
#define HDIM 256
#define CTXD 128
#define PRED 12
#define STR 72            // smem tile k-stride in bf16 (64 + 8 pad)

// packed weight layout (bf16 elements, hi plane; lo plane at +WTOT)
#define O_WHH0 0L          // 768 x 256
#define O_WIH1 196608L     // 768 x 256
#define O_WHH1 393216L     // 768 x 256
#define O_WHHS 589824L     // 768 x 256
#define O_WCTX 786432L     // 768 x 128  (Wihs cols 0..127)
#define O_PA   884736L     // 192 x 256  (P1 rows 0..127, A1 rows 128..191)
#define WTOT   933888L

// --- static device scratch ---
__device__ float g_h0a[BMAX * HDIM];
__device__ float g_h0b[BMAX * HDIM];
__device__ float g_h1a[BMAX * HDIM];
__device__ float g_h1b[BMAX * HDIM];
__device__ float g_obsin[8 * BMAX * 6];
__device__ float g_ctxp[BMAX * CTXD];
__device__ float g_dynA[BMAX * 6];
__device__ float g_dynB[BMAX * 6];
__device__ float g_gictx[BMAX * 768];     // hoisted ctx input-gates
__device__ float g_wdyn0[768 * 8];        // Wih0 (K=6, padded 8), fp32
__device__ float g_wdynS[768 * 8];        // Wihs cols 128..133, fp32
__device__ __nv_bfloat16 g_wpack[2 * WTOT];

// ---------------------------------------------------------------------------
__global__ void zero_kernel(float* __restrict__ p, int n) {
    int stride = gridDim.x * blockDim.x;
    for (int i = blockIdx.x * blockDim.x + threadIdx.x; i * 4 < n; i += stride)
        ((float4*)p)[i] = make_float4(0.f, 0.f, 0.f, 0.f);
}

// pack [rows, K] slice of src (row stride ld, col offset koff) -> hi/lo bf16
__global__ void pack_kernel(const float* __restrict__ W, int rows, int ld, int koff,
                            int K, int Kpad, long dst, __nv_bfloat16* __restrict__ wp) {
    int i = blockIdx.x * blockDim.x + threadIdx.x;
    if (i >= rows * Kpad) return;
    int r = i / Kpad, k = i - r * Kpad;
    float v = (k < K) ? W[(size_t)r * ld + koff + k] : 0.f;
    __nv_bfloat16 h = __float2bfloat16(v);
    wp[dst + i] = h;
    wp[WTOT + dst + i] = __float2bfloat16(v - __bfloat162float(h));
}

// compact fp32 dyn weights: dst[r*8+q] = src[r*ld + koff + q] (q<6)
__global__ void wdyn_pack_kernel(const float* __restrict__ src, int ld, int koff,
                                 float* __restrict__ dst) {
    int i = blockIdx.x * blockDim.x + threadIdx.x;
    if (i >= 768 * 8) return;
    int r = i >> 3, q = i & 7;
    dst[i] = (q < 6) ? src[(size_t)r * ld + koff + q] : 0.f;
}

// ---------------------------------------------------------------------------
__global__ void prep_kernel(const float* __restrict__ traj,
                            const float* __restrict__ me,
                            float* __restrict__ obsin,
                            float* __restrict__ dyn, int B, int T) {
    int b = blockIdx.x * blockDim.x + threadIdx.x;
    if (b >= B) return;
    float vx[8], vy[8], mx[8], my_[8];
    int TS = T - 1;
    if (TS > 8) TS = 8;
    for (int t = 0; t < TS; t++) {
        vx[t]  = traj[((size_t)(t + 1) * B + b) * 2 + 0] - traj[((size_t)t * B + b) * 2 + 0];
        vy[t]  = traj[((size_t)(t + 1) * B + b) * 2 + 1] - traj[((size_t)t * B + b) * 2 + 1];
        mx[t]  = me[((size_t)(t + 1) * B + b) * 2 + 0] - me[((size_t)t * B + b) * 2 + 0];
        my_[t] = me[((size_t)(t + 1) * B + b) * 2 + 1] - me[((size_t)t * B + b) * 2 + 1];
    }
    for (int t = 0; t < TS; t++) {
        int ta = (t == 0) ? 1 : t;
        float ax = vx[ta] - vx[ta - 1];
        float ay = vy[ta] - vy[ta - 1];
        float* o = obsin + ((size_t)t * B + b) * 6;
        o[0] = vx[t]; o[1] = vy[t];
        o[2] = mx[t]; o[3] = my_[t];
        o[4] = ax;    o[5] = ay;
    }
    dyn[(size_t)b * 6 + 0] = vx[TS - 1];
    dyn[(size_t)b * 6 + 1] = vy[TS - 1];
    dyn[(size_t)b * 6 + 2] = vx[TS - 1] - vx[TS - 2];
    dyn[(size_t)b * 6 + 3] = vy[TS - 1] - vy[TS - 2];
    dyn[(size_t)b * 6 + 4] = mx[TS - 1];
    dyn[(size_t)b * 6 + 5] = my_[TS - 1];
}

// ---------------------------------------------------------------------------
__global__ __launch_bounds__(256) void ctx_kernel(const float* __restrict__ ctx,
                                                  const float* __restrict__ Cw,
                                                  const float* __restrict__ cb,
                                                  float* __restrict__ outp, int B) {
    __shared__ float Cs[64][128];
    __shared__ float Wc[16][128];
    int tid = threadIdx.x;
    int m0 = blockIdx.x * 64;
    for (int i = tid; i < 64 * 128 / 4; i += 256) {
        int m = m0 + (i * 4) / 128;
        float4 v = make_float4(0.f, 0.f, 0.f, 0.f);
        if (m < B) v = *(const float4*)&ctx[(size_t)m0 * 128 + i * 4];
        ((float4*)Cs)[i] = v;
    }
    __syncthreads();
    int w = tid >> 5, lane = tid & 31;
    float acc[8][4];
#pragma unroll
    for (int i = 0; i < 8; i++)
#pragma unroll
        for (int u = 0; u < 4; u++) acc[i][u] = 0.f;

    for (int k0 = 0; k0 < 128; k0 += 16) {
        for (int i = tid; i < 16 * 128; i += 256) {
            int kk = i & 15, u = i >> 4;
            Wc[kk][u] = Cw[(size_t)u * 128 + k0 + kk];
        }
        __syncthreads();
#pragma unroll
        for (int kk = 0; kk < 16; kk++) {
            float wv[4];
#pragma unroll
            for (int u = 0; u < 4; u++) wv[u] = Wc[kk][lane * 4 + u];
#pragma unroll
            for (int i = 0; i < 8; i++) {
                float a = Cs[w * 8 + i][k0 + kk];
#pragma unroll
                for (int u = 0; u < 4; u++) acc[i][u] += a * wv[u];
            }
        }
        __syncthreads();
    }
#pragma unroll
    for (int i = 0; i < 8; i++) {
        int m = m0 + w * 8 + i;
        if (m >= B) continue;
#pragma unroll
        for (int u = 0; u < 4; u++) {
            int ug = lane * 4 + u;
            outp[(size_t)m * 128 + ug] = acc[i][u] + cb[ug];
        }
    }
}

// ---------------------------------------------------------------------------
// tensor-core helpers
// ---------------------------------------------------------------------------
__device__ __forceinline__ void mma_bf16(float* c, const uint32_t* a, uint32_t b0, uint32_t b1) {
    asm volatile(
        "mma.sync.aligned.m16n8k16.row.col.f32.bf16.bf16.f32 "
        "{%0,%1,%2,%3}, {%4,%5,%6,%7}, {%8,%9}, {%0,%1,%2,%3};\n"
        : "+f"(c[0]), "+f"(c[1]), "+f"(c[2]), "+f"(c[3])
        : "r"(a[0]), "r"(a[1]), "r"(a[2]), "r"(a[3]), "r"(b0), "r"(b1));
}

__device__ __forceinline__ void ldsm_x4(uint32_t* r, const __nv_bfloat16* base,
                                        int row, int col, int lane) {
    int g = lane >> 3, rr = lane & 7;
    const __nv_bfloat16* p = base + (size_t)(row + (g & 1) * 8 + rr) * STR + col + (g >> 1) * 8;
    uint32_t addr = (uint32_t)__cvta_generic_to_shared(p);
    asm volatile("ldmatrix.sync.aligned.m8n8.x4.shared.b16 {%0,%1,%2,%3}, [%4];"
                 : "=r"(r[0]), "=r"(r[1]), "=r"(r[2]), "=r"(r[3]) : "r"(addr));
}

__device__ __forceinline__ void ldsm_x2(uint32_t* r, const __nv_bfloat16* base,
                                        int row, int col, int lane) {
    int l = lane & 15;
    int g = l >> 3, rr = l & 7;
    const __nv_bfloat16* p = base + (size_t)(row + rr) * STR + col + g * 8;
    uint32_t addr = (uint32_t)__cvta_generic_to_shared(p);
    asm volatile("ldmatrix.sync.aligned.m8n8.x2.shared.b16 {%0,%1}, [%2];"
                 : "=r"(r[0]), "=r"(r[1]) : "r"(addr));
}

template<bool ALT>
__device__ __forceinline__ void mma_all(float (&accA)[2][6][4], float (&accH)[2][2][4],
                                        uint32_t a[2][4], uint32_t b[6][2]) {
#pragma unroll
    for (int mf = 0; mf < 2; mf++)
#pragma unroll
        for (int f = 0; f < 6; f++) {
            float* c = (ALT && f >= 4) ? accH[mf][f - 4] : accA[mf][f];
            mma_bf16(c, a[mf], b[f][0], b[f][1]);
        }
}

// acc += split_bf16(X[128 x K]) @ split_bf16(W[96 x K])^T
// K must be a multiple of 64; X row stride ldx multiple of 4.
// Weight row mapping: grow = (r>>5)*plane_stride + n0 + (r&31).
template<bool ALT>
__device__ __forceinline__ void gemm_phase(
    const float* __restrict__ X, int ldx, int K,
    const __nv_bfloat16* __restrict__ wHi, const __nv_bfloat16* __restrict__ wLo,
    int ldwp, int plane_stride,
    int m0, int n0, int B,
    __nv_bfloat16* Ahi, __nv_bfloat16* Alo, __nv_bfloat16* Whi, __nv_bfloat16* Wlo,
    float (&accA)[2][6][4], float (&accH)[2][2][4]) {
    const int tid = threadIdx.x;
    const int lane = tid & 31;
    const int w = tid >> 5;
    const int mw = w >> 1;
    const int nw = w & 1;

    for (int k0 = 0; k0 < K; k0 += 64) {
        __syncthreads();
        // stage W: 96 rows x 64 cols (hi + lo)
        for (int i = tid; i < 768; i += 256) {
            int r = i >> 3, q = i & 7;
            int grow = (r >> 5) * plane_stride + n0 + (r & 31);
            size_t so = (size_t)grow * ldwp + k0 + q * 8;
            *(uint4*)(Whi + (size_t)r * STR + q * 8) = *(const uint4*)(wHi + so);
            *(uint4*)(Wlo + (size_t)r * STR + q * 8) = *(const uint4*)(wLo + so);
        }
        // stage A with on-the-fly hi/lo split
        for (int i = tid; i < 2048; i += 256) {
            int r = i >> 4, c = (i & 15) * 4;
            int m = m0 + r;
            float4 v = make_float4(0.f, 0.f, 0.f, 0.f);
            if (m < B) v = *(const float4*)(X + (size_t)m * ldx + k0 + c);
            __nv_bfloat162 h0 = __floats2bfloat162_rn(v.x, v.y);
            __nv_bfloat162 h1 = __floats2bfloat162_rn(v.z, v.w);
            *(__nv_bfloat162*)(Ahi + (size_t)r * STR + c)     = h0;
            *(__nv_bfloat162*)(Ahi + (size_t)r * STR + c + 2) = h1;
            __nv_bfloat162 l0 = __floats2bfloat162_rn(v.x - __bfloat162float(h0.x),
                                                      v.y - __bfloat162float(h0.y));
            __nv_bfloat162 l1 = __floats2bfloat162_rn(v.z - __bfloat162float(h1.x),
                                                      v.w - __bfloat162float(h1.y));
            *(__nv_bfloat162*)(Alo + (size_t)r * STR + c)     = l0;
            *(__nv_bfloat162*)(Alo + (size_t)r * STR + c + 2) = l1;
        }
        __syncthreads();
#pragma unroll
        for (int ks = 0; ks < 4; ks++) {
            uint32_t ah[2][4], al[2][4], b[6][2];
            ldsm_x4(ah[0], Ahi, mw * 32,      ks * 16, lane);
            ldsm_x4(ah[1], Ahi, mw * 32 + 16, ks * 16, lane);
            ldsm_x4(al[0], Alo, mw * 32,      ks * 16, lane);
            ldsm_x4(al[1], Alo, mw * 32 + 16, ks * 16, lane);
#pragma unroll
            for (int f = 0; f < 6; f++) ldsm_x2(b[f], Whi, (f * 2 + nw) * 8, ks * 16, lane);
            mma_all<ALT>(accA, accH, ah, b);   // hi*hi
            mma_all<ALT>(accA, accH, al, b);   // lo*hi
#pragma unroll
            for (int f = 0; f < 6; f++) ldsm_x2(b[f], Wlo, (f * 2 + nw) * 8, ks * 16, lane);
            mma_all<ALT>(accA, accH, ah, b);   // hi*lo
        }
    }
}

// ---------------------------------------------------------------------------
// Fused GRU cell. smem: staging tiles (64512B) unioned with gbuf (73728B),
// plus dyn-weight cache (3072B) after gbuf.
// mode 0: full gate epilogue; mode 1: store raw input-gates to gi_out.
// ---------------------------------------------------------------------------
#define GRU_SMEM 76800

__global__ __launch_bounds__(256) void gru_mma_kernel(
    const float* __restrict__ X1, int ld1, int k1,
    const float* __restrict__ Hin, int do_hidden,
    const __nv_bfloat16* __restrict__ wpack,
    long wih_off, int wih_ldp, long whh_off,
    const float* __restrict__ gi_ext,
    const float* __restrict__ wdyn,
    const float* __restrict__ xdyn, int ld_dyn,
    const float* __restrict__ bih, const float* __restrict__ bhh,
    float* __restrict__ Hout, float* __restrict__ gi_out, int B, int mode) {
    extern __shared__ char sm_[];
    __nv_bfloat16* Ahi = (__nv_bfloat16*)sm_;
    __nv_bfloat16* Alo = Ahi + 128 * STR;
    __nv_bfloat16* Whi = Alo + 128 * STR;
    __nv_bfloat16* Wlo = Whi + 96 * STR;
    float* gbuf = (float*)sm_;
    float* wd_s = (float*)(sm_ + 73728);

    const int tid = threadIdx.x;
    const int lane = tid & 31;
    const int w = tid >> 5;
    const int mw = w >> 1;
    const int nw = w & 1;
    const int m0 = blockIdx.x * 128;
    const int n0 = blockIdx.y * 32;

    // stage compact dyn weights for this block's 32 cols (3 planes x 32 x 8)
    if (wdyn != nullptr) {
        for (int i = tid; i < 768; i += 256) {
            int rr = i >> 3, q = i & 7;
            int p = rr >> 5, c = rr & 31;
            wd_s[i] = wdyn[((size_t)(p * 256) + n0 + c) * 8 + q];
        }
    }

    float accA[2][6][4];
    float accH[2][2][4];
#pragma unroll
    for (int mf = 0; mf < 2; mf++) {
#pragma unroll
        for (int f = 0; f < 6; f++)
#pragma unroll
            for (int u = 0; u < 4; u++) accA[mf][f][u] = 0.f;
#pragma unroll
        for (int f = 0; f < 2; f++)
#pragma unroll
            for (int u = 0; u < 4; u++) accH[mf][f][u] = 0.f;
    }

    if (X1 != nullptr)
        gemm_phase<false>(X1, ld1, k1, wpack + wih_off, wpack + WTOT + wih_off,
                          wih_ldp, 256, m0, n0, B, Ahi, Alo, Whi, Wlo, accA, accH);
    if (do_hidden)
        gemm_phase<true>(Hin, 256, 256, wpack + whh_off, wpack + WTOT + whh_off,
                         256, 256, m0, n0, B, Ahi, Alo, Whi, Wlo, accA, accH);

    // ---- scatter accumulators to gate buffer ----
    __syncthreads();
    {
        int r0 = mw * 32 + (lane >> 2);
        int cl = (lane & 3) * 2;
#pragma unroll
        for (int mf = 0; mf < 2; mf++) {
#pragma unroll
            for (int f = 0; f < 6; f++) {
                int gf = f * 2 + nw;
                int p = gf >> 2;
                int col = ((gf * 8) & 31) + cl;
                int rr = r0 + mf * 16;
                float* g0 = gbuf + ((size_t)(p * 128 + rr)) * 36 + col;
                g0[0] = accA[mf][f][0]; g0[1] = accA[mf][f][1];
                g0[8 * 36] = accA[mf][f][2]; g0[8 * 36 + 1] = accA[mf][f][3];
                if (f >= 4) {
                    float* g1 = gbuf + ((size_t)(3 * 128 + rr)) * 36 + col;
                    g1[0] = accH[mf][f - 4][0]; g1[1] = accH[mf][f - 4][1];
                    g1[8 * 36] = accH[mf][f - 4][2]; g1[8 * 36 + 1] = accH[mf][f - 4][3];
                }
            }
        }
    }
    __syncthreads();

    if (mode == 1) {
        // store raw input-gate planes (r,z,ig) to gi_out[B,768]
        for (int i = tid; i < 3 * 128 * 32; i += 256) {
            int p = i >> 12; int rem = i & 4095;
            int row = rem >> 5; int col = rem & 31;
            int m = m0 + row;
            if (m < B)
                gi_out[(size_t)m * 768 + p * 256 + n0 + col] =
                    gbuf[(size_t)(p * 128 + row) * 36 + col];
        }
        return;
    }

    // ---- gate epilogue ----
    {
        int row = tid >> 1;
        int m = m0 + row;
        int cbase = (tid & 1) * 16;
        bool valid = (m < B);
        float xd[6];
#pragma unroll
        for (int q = 0; q < 6; q++) xd[q] = 0.f;
        if (wdyn != nullptr && valid) {
#pragma unroll
            for (int q = 0; q < 6; q++) xd[q] = xdyn[(size_t)m * ld_dyn + q];
        }
        float ov[16];
#pragma unroll
        for (int c4 = 0; c4 < 4; c4++) {
            int col = cbase + c4 * 4;
            int jg = n0 + col;
            float grv[4], gzv[4], giv[4], ghv[4], hpv[4];
            *(float4*)grv = *(float4*)(gbuf + (size_t)(0 * 128 + row) * 36 + col);
            *(float4*)gzv = *(float4*)(gbuf + (size_t)(1 * 128 + row) * 36 + col);
            *(float4*)giv = *(float4*)(gbuf + (size_t)(2 * 128 + row) * 36 + col);
            *(float4*)ghv = *(float4*)(gbuf + (size_t)(3 * 128 + row) * 36 + col);
            if (valid) *(float4*)hpv = *(const float4*)(Hin + (size_t)m * 256 + jg);
            else { hpv[0] = hpv[1] = hpv[2] = hpv[3] = 0.f; }
            if (gi_ext != nullptr && valid) {
                float e0[4], e1[4], e2[4];
                *(float4*)e0 = *(const float4*)(gi_ext + (size_t)m * 768 + jg);
                *(float4*)e1 = *(const float4*)(gi_ext + (size_t)m * 768 + 256 + jg);
                *(float4*)e2 = *(const float4*)(gi_ext + (size_t)m * 768 + 512 + jg);
#pragma unroll
                for (int cc = 0; cc < 4; cc++) {
                    grv[cc] += e0[cc]; gzv[cc] += e1[cc]; giv[cc] += e2[cc];
                }
            }
            if (wdyn != nullptr) {
#pragma unroll
                for (int cc = 0; cc < 4; cc++) {
                    int cl_ = col + cc;
                    const float* w0 = wd_s + (0 * 32 + cl_) * 8;
                    const float* w1 = wd_s + (1 * 32 + cl_) * 8;
                    const float* w2 = wd_s + (2 * 32 + cl_) * 8;
#pragma unroll
                    for (int q = 0; q < 6; q++) {
                        grv[cc] += xd[q] * w0[q];
                        gzv[cc] += xd[q] * w1[q];
                        giv[cc] += xd[q] * w2[q];
                    }
                }
            }
#pragma unroll
            for (int cc = 0; cc < 4; cc++) {
                int j = jg + cc;
                float r_ = 1.f / (1.f + expf(-(grv[cc] + bih[j] + bhh[j])));
                float z_ = 1.f / (1.f + expf(-(gzv[cc] + bih[256 + j] + bhh[256 + j])));
                float n_ = tanhf(giv[cc] + bih[512 + j] + r_ * (ghv[cc] + bhh[512 + j]));
                ov[c4 * 4 + cc] = (1.f - z_) * n_ + z_ * hpv[cc];
            }
        }
        if (valid) {
#pragma unroll
            for (int c4 = 0; c4 < 4; c4++)
                *(float4*)(Hout + (size_t)m * 256 + n0 + cbase + c4 * 4) = *(float4*)(ov + c4 * 4);
        }
    }
}

// ---------------------------------------------------------------------------
// projection heads: stage1 [B,192] = GELU(H @ [P1;A1]^T + b) via bf16x3 mma,
// stage2 tiny fp32 head GEMMs. Block = 128 rows, two 96-col phases.
// ---------------------------------------------------------------------------
#define PROJ_SMEM (64512 + 128 * 196 * 4)   // tiles + D1 = 164864

__device__ __forceinline__ void proj_scatter(float (&accA)[2][6][4], float* D1, int n0,
                                             const float* __restrict__ p1b,
                                             const float* __restrict__ a1b,
                                             int mw, int nw, int lane) {
    int r0 = mw * 32 + (lane >> 2);
    int cl = (lane & 3) * 2;
#pragma unroll
    for (int mf = 0; mf < 2; mf++)
#pragma unroll
        for (int f = 0; f < 6; f++) {
            int gf = f * 2 + nw;
            int colb = n0 + gf * 8 + cl;
            int rr = r0 + mf * 16;
#pragma unroll
            for (int jj = 0; jj < 2; jj++) {
                int col = colb + jj;
                float b = (col < 128) ? p1b[col] : a1b[col - 128];
                float v0 = accA[mf][f][jj] + b;
                float v1 = accA[mf][f][2 + jj] + b;
                D1[(size_t)rr * 196 + col] = v0 * normcdff(v0);
                D1[(size_t)(rr + 8) * 196 + col] = v1 * normcdff(v1);
            }
        }
}

__global__ __launch_bounds__(256) void proj_mma_kernel(
    const float* __restrict__ H,
    const __nv_bfloat16* __restrict__ wpack,
    const float* __restrict__ p1b, const float* __restrict__ a1b,
    const float* __restrict__ P2, const float* __restrict__ p2b,
    const float* __restrict__ A2, const float* __restrict__ a2b,
    float* __restrict__ out, float* __restrict__ dyn, int B, int tstep) {
    extern __shared__ char sm_[];
    __nv_bfloat16* Ahi = (__nv_bfloat16*)sm_;
    __nv_bfloat16* Alo = Ahi + 128 * STR;
    __nv_bfloat16* Whi = Alo + 128 * STR;
    __nv_bfloat16* Wlo = Whi + 96 * STR;
    float* D1 = (float*)(sm_ + 64512);
    float* wsm = (float*)sm_;   // reused after GEMM for head weights

    const int tid = threadIdx.x;
    const int lane = tid & 31;
    const int w = tid >> 5;
    const int mw = w >> 1;
    const int nw = w & 1;
    const int m0 = blockIdx.x * 128;

    float accA[2][6][4];
    float accH[2][2][4];
#pragma unroll
    for (int mf = 0; mf < 2; mf++) {
#pragma unroll
        for (int f = 0; f < 6; f++)
#pragma unroll
            for (int u = 0; u < 4; u++) accA[mf][f][u] = 0.f;
#pragma unroll
        for (int f = 0; f < 2; f++)
#pragma unroll
            for (int u = 0; u < 4; u++) accH[mf][f][u] = 0.f;
    }

    gemm_phase<false>(H, 256, 256, wpack + O_PA, wpack + WTOT + O_PA,
                      256, 32, m0, 0, B, Ahi, Alo, Whi, Wlo, accA, accH);
    proj_scatter(accA, D1, 0, p1b, a1b, mw, nw, lane);
#pragma unroll
    for (int mf = 0; mf < 2; mf++)
#pragma unroll
        for (int f = 0; f < 6; f++)
#pragma unroll
            for (int u = 0; u < 4; u++) accA[mf][f][u] = 0.f;
    gemm_phase<false>(H, 256, 256, wpack + O_PA, wpack + WTOT + O_PA,
                      256, 32, m0, 96, B, Ahi, Alo, Whi, Wlo, accA, accH);
    proj_scatter(accA, D1, 96, p1b, a1b, mw, nw, lane);
    __syncthreads();

    // stage head weights into (now free) tile smem
    for (int i = tid; i < 512; i += 256) wsm[i] = P2[i];
    if (tid < 128) wsm[512 + tid] = A2[tid];
    if (tid < 4) wsm[640 + tid] = p2b[tid];
    if (tid < 2) wsm[644 + tid] = a2b[tid];
    __syncthreads();

    // delta head: 128 rows x 4 outs, K=128
#pragma unroll
    for (int it = 0; it < 2; it++) {
        int idx = tid + it * 256;
        int s = idx >> 2, o = idx & 3;
        float a = wsm[640 + o];
        const float* w2 = wsm + o * 128;
        const float* d = D1 + (size_t)s * 196;
#pragma unroll 8
        for (int k = 0; k < 128; k++) a += d[k] * w2[k];
        int m = m0 + s;
        if (m < B) {
            out[(size_t)m * 48 + tstep * 4 + o] = a;
            dyn[(size_t)m * 6 + (o < 2 ? o : o + 2)] = a;
        }
    }
    // accel head: 128 rows x 2 outs, K=64
    {
        int s = tid >> 1, o = tid & 1;
        float a = wsm[644 + o];
        const float* w2 = wsm + 512 + o * 64;
        const float* d = D1 + (size_t)s * 196 + 128;
#pragma unroll 8
        for (int k = 0; k < 64; k++) a += d[k] * w2[k];
        int m = m0 + s;
        if (m < B) dyn[(size_t)m * 6 + 2 + o] = a;
    }
}

// ---------------------------------------------------------------------------
extern "C" void kernel_launch(void* const* d_in, const int* in_sizes, int n_in,
                              void* d_out, int out_size) {
    const float* ctx      = (const float*)d_in[0];
    const float* obs_traj = (const float*)d_in[1];
    const float* obs_Me   = (const float*)d_in[2];
    const float* Wih0 = (const float*)d_in[3];
    const float* Whh0 = (const float*)d_in[4];
    const float* bih0 = (const float*)d_in[5];
    const float* bhh0 = (const float*)d_in[6];
    const float* Wih1 = (const float*)d_in[7];
    const float* Whh1 = (const float*)d_in[8];
    const float* bih1 = (const float*)d_in[9];
    const float* bhh1 = (const float*)d_in[10];
    const float* Wihs = (const float*)d_in[11];
    const float* Whhs = (const float*)d_in[12];
    const float* bihs = (const float*)d_in[13];
    const float* bhhs = (const float*)d_in[14];
    const float* P1  = (const float*)d_in[15];
    const float* p1b = (const float*)d_in[16];
    const float* P2  = (const float*)d_in[17];
    const float* p2b = (const float*)d_in[18];
    const float* A1  = (const float*)d_in[19];
    const float* a1b = (const float*)d_in[20];
    const float* A2  = (const float*)d_in[21];
    const float* a2b = (const float*)d_in[22];
    const float* Cw  = (const float*)d_in[23];
    const float* cb  = (const float*)d_in[24];
    float* out = (float*)d_out;

    int B = in_sizes[0] / CTXD;
    if (B > BMAX) B = BMAX;
    int T = in_sizes[1] / (2 * B);
    int TS = T - 1;

    float *h0a, *h0b, *h1a, *h1b, *obsin, *ctxp, *dynA, *dynB, *gictx, *wd0, *wdS;
    __nv_bfloat16* wpk;
    cudaGetSymbolAddress((void**)&h0a, g_h0a);
    cudaGetSymbolAddress((void**)&h0b, g_h0b);
    cudaGetSymbolAddress((void**)&h1a, g_h1a);
    cudaGetSymbolAddress((void**)&h1b, g_h1b);
    cudaGetSymbolAddress((void**)&obsin, g_obsin);
    cudaGetSymbolAddress((void**)&ctxp, g_ctxp);
    cudaGetSymbolAddress((void**)&dynA, g_dynA);
    cudaGetSymbolAddress((void**)&dynB, g_dynB);
    cudaGetSymbolAddress((void**)&gictx, g_gictx);
    cudaGetSymbolAddress((void**)&wd0, g_wdyn0);
    cudaGetSymbolAddress((void**)&wdS, g_wdynS);
    cudaGetSymbolAddress((void**)&wpk, g_wpack);

    cudaFuncSetAttribute(gru_mma_kernel, cudaFuncAttributeMaxDynamicSharedMemorySize, GRU_SMEM);
    cudaFuncSetAttribute(proj_mma_kernel, cudaFuncAttributeMaxDynamicSharedMemorySize, PROJ_SMEM);

    // pack weights -> bf16 hi/lo (+ fp32 compact dyn slices)
    pack_kernel<<<768, 256>>>(Whh0, 768, 256, 0, 256, 256, O_WHH0, wpk);
    pack_kernel<<<768, 256>>>(Wih1, 768, 256, 0, 256, 256, O_WIH1, wpk);
    pack_kernel<<<768, 256>>>(Whh1, 768, 256, 0, 256, 256, O_WHH1, wpk);
    pack_kernel<<<768, 256>>>(Whhs, 768, 256, 0, 256, 256, O_WHHS, wpk);
    pack_kernel<<<384, 256>>>(Wihs, 768, 134, 0, 128, 128, O_WCTX, wpk);
    pack_kernel<<<128, 256>>>(P1, 128, 256, 0, 256, 256, O_PA, wpk);
    pack_kernel<<<64, 256>>>(A1, 64, 256, 0, 256, 256, O_PA + 128L * 256, wpk);
    wdyn_pack_kernel<<<24, 256>>>(Wih0, 6, 0, wd0);
    wdyn_pack_kernel<<<24, 256>>>(Wihs, 134, 128, wdS);

    zero_kernel<<<264, 256>>>(h0a, B * HDIM);
    zero_kernel<<<264, 256>>>(h1a, B * HDIM);
    prep_kernel<<<(B + 255) / 256, 256>>>(obs_traj, obs_Me, obsin, dynA, B, T);
    ctx_kernel<<<(B + 63) / 64, 256>>>(ctx, Cw, cb, ctxp, B);

    dim3 cgrid((B + 127) / 128, 8);

    // hoisted decoder ctx input-gates: gi_ctx = ctxp @ Wihs[:, :128].T
    gru_mma_kernel<<<cgrid, 256, GRU_SMEM>>>(ctxp, 128, 128, nullptr, 0,
                                             wpk, O_WCTX, 128, 0L,
                                             nullptr, nullptr, nullptr, 0,
                                             bihs, bhhs, nullptr, gictx, B, 1);

    // encoder
    float *h0i = h0a, *h0o = h0b, *h1i = h1a, *h1o = h1b;
    for (int t = 0; t < TS; t++) {
        gru_mma_kernel<<<cgrid, 256, GRU_SMEM>>>(nullptr, 0, 0,
                                                 h0i, (t > 0) ? 1 : 0,
                                                 wpk, 0L, 0, O_WHH0,
                                                 nullptr, wd0, obsin + (size_t)t * B * 6, 6,
                                                 bih0, bhh0, h0o, nullptr, B, 0);
        gru_mma_kernel<<<cgrid, 256, GRU_SMEM>>>(h0o, 256, 256,
                                                 h1i, (t > 0) ? 1 : 0,
                                                 wpk, O_WIH1, 256, O_WHH1,
                                                 nullptr, nullptr, nullptr, 0,
                                                 bih1, bhh1, h1o, nullptr, B, 0);
        float* t0 = h0i; h0i = h0o; h0o = t0;
        float* t1 = h1i; h1i = h1o; h1o = t1;
    }

    // decoder
    float* dhi = h1i;
    float* dho = h1o;
    float* dyi = dynA;
    float* dyo = dynB;
    for (int s = 0; s < PRED; s++) {
        gru_mma_kernel<<<cgrid, 256, GRU_SMEM>>>(nullptr, 0, 0,
                                                 dhi, 1,
                                                 wpk, 0L, 0, O_WHHS,
                                                 gictx, wdS, dyi, 6,
                                                 bihs, bhhs, dho, nullptr, B, 0);
        proj_mma_kernel<<<(B + 127) / 128, 256, PROJ_SMEM>>>(dho, wpk, p1b, a1b,
                                                             P2, p2b, A2, a2b,
                                                             out, dyo, B, s);
        float* td = dhi; dhi = dho; dho = td;
        float* ty_ = dyi; dyi = dyo; dyo = ty_;
    }
}